// round 8
// baseline (speedup 1.0000x reference)
#include <cuda_runtime.h>
#include <cuda_bf16.h>
#include <cstdint>

// Problem constants
#define BB 4
#define SS 2048
#define DM 1024
#define HH 16
#define HD 64
#define MROWS (BB * SS)   // 8192

// Q pre-scale: (1/sqrt(D)) * log2(e) folded into Q projection output.
#define QSCALE 0.04508422002778011f

// Scratch (allocation-free rule: __device__ globals)
__device__ __nv_bfloat16 g_Aqh[MROWS * DM], g_Aql[MROWS * DM];
__device__ __nv_bfloat16 g_Akh[MROWS * DM], g_Akl[MROWS * DM];
__device__ __nv_bfloat16 g_Avh[MROWS * DM], g_Avl[MROWS * DM];
__device__ __nv_bfloat16 g_Wqh[DM * DM], g_Wql[DM * DM];
__device__ __nv_bfloat16 g_Wkh[DM * DM], g_Wkl[DM * DM];
__device__ __nv_bfloat16 g_Wvh[DM * DM], g_Wvl[DM * DM];
__device__ __nv_bfloat16 g_Woh[DM * DM], g_Wol[DM * DM];
__device__ __nv_bfloat16 g_Qh[MROWS * DM], g_Ql[MROWS * DM];
__device__ __nv_bfloat16 g_Kh[MROWS * DM], g_Kl[MROWS * DM];
__device__ __nv_bfloat16 g_Vh[MROWS * DM], g_Vl[MROWS * DM];
__device__ __nv_bfloat16 g_Xh[MROWS * DM], g_Xl[MROWS * DM];

// ---------------------------------------------------------------------------
// Portable (sm_80+) tensor-core helpers
// ---------------------------------------------------------------------------
__device__ __forceinline__ uint32_t smem_to_u32(const void* p) {
    uint32_t a;
    asm("{ .reg .u64 t; cvta.to.shared.u64 t, %1; cvt.u32.u64 %0, t; }"
        : "=r"(a) : "l"(p));
    return a;
}

__device__ __forceinline__ void ldsm_x4(uint32_t& r0, uint32_t& r1,
                                        uint32_t& r2, uint32_t& r3,
                                        uint32_t addr) {
    asm volatile("ldmatrix.sync.aligned.m8n8.x4.shared.b16 {%0,%1,%2,%3}, [%4];"
                 : "=r"(r0), "=r"(r1), "=r"(r2), "=r"(r3) : "r"(addr));
}

__device__ __forceinline__ void ldsm_x4_t(uint32_t& r0, uint32_t& r1,
                                          uint32_t& r2, uint32_t& r3,
                                          uint32_t addr) {
    asm volatile("ldmatrix.sync.aligned.m8n8.x4.trans.shared.b16 {%0,%1,%2,%3}, [%4];"
                 : "=r"(r0), "=r"(r1), "=r"(r2), "=r"(r3) : "r"(addr));
}

__device__ __forceinline__ void mma_bf16(float* c, const uint32_t* a,
                                         uint32_t b0, uint32_t b1) {
    asm volatile(
        "mma.sync.aligned.m16n8k16.row.col.f32.bf16.bf16.f32 "
        "{%0,%1,%2,%3}, {%4,%5,%6,%7}, {%8,%9}, {%0,%1,%2,%3};"
        : "+f"(c[0]), "+f"(c[1]), "+f"(c[2]), "+f"(c[3])
        : "r"(a[0]), "r"(a[1]), "r"(a[2]), "r"(a[3]), "r"(b0), "r"(b1));
}

__device__ __forceinline__ float ex2(float x) {
    float y;
    asm("ex2.approx.ftz.f32 %0, %1;" : "=f"(y) : "f"(x));
    return y;
}

#define CP_ASYNC_16(smem_u32, gptr) \
    asm volatile("cp.async.cg.shared.global [%0], [%1], 16;" \
        :: "r"(smem_u32), "l"(gptr) : "memory")
#define CP_ASYNC_COMMIT() asm volatile("cp.async.commit_group;" ::: "memory")
#define CP_ASYNC_WAIT1() asm volatile("cp.async.wait_group 1;" ::: "memory")
#define CP_ASYNC_WAIT0() asm volatile("cp.async.wait_group 0;" ::: "memory")

// x = hi + lo (bf16 pair), packed two-at-a-time into bf16x2 registers
__device__ __forceinline__ void split2(float x, float y, uint32_t& hi, uint32_t& lo) {
    __nv_bfloat16 hx = __float2bfloat16_rn(x);
    __nv_bfloat16 hy = __float2bfloat16_rn(y);
    __nv_bfloat16 lx = __float2bfloat16_rn(x - __bfloat162float(hx));
    __nv_bfloat16 ly = __float2bfloat16_rn(y - __bfloat162float(hy));
    hi = ((uint32_t)__bfloat16_as_ushort(hy) << 16) | __bfloat16_as_ushort(hx);
    lo = ((uint32_t)__bfloat16_as_ushort(ly) << 16) | __bfloat16_as_ushort(lx);
}

__device__ __forceinline__ void split_body(const float* __restrict__ x,
                                           __nv_bfloat16* __restrict__ hi,
                                           __nv_bfloat16* __restrict__ lo, int n4)
{
    int i = blockIdx.x * blockDim.x + threadIdx.x;
    int stride = gridDim.x * blockDim.x;
    for (; i < n4; i += stride) {
        float4 v = ((const float4*)x)[i];
        uint32_t h0, l0, h1, l1;
        split2(v.x, v.y, h0, l0);
        split2(v.z, v.w, h1, l1);
        ((uint2*)hi)[i] = make_uint2(h0, h1);
        ((uint2*)lo)[i] = make_uint2(l0, l1);
    }
}

__global__ __launch_bounds__(256) void split_inputs_kernel(
    const float* __restrict__ q, const float* __restrict__ k,
    const float* __restrict__ v)
{
    const int n4 = MROWS * DM / 4;
    if (blockIdx.z == 0)      split_body(q, g_Aqh, g_Aql, n4);
    else if (blockIdx.z == 1) split_body(k, g_Akh, g_Akl, n4);
    else                      split_body(v, g_Avh, g_Avl, n4);
}

__global__ __launch_bounds__(256) void split_weights_kernel(
    const float* __restrict__ wq, const float* __restrict__ wk,
    const float* __restrict__ wv, const float* __restrict__ wo)
{
    const int n4 = DM * DM / 4;
    if (blockIdx.z == 0)      split_body(wq, g_Wqh, g_Wql, n4);
    else if (blockIdx.z == 1) split_body(wk, g_Wkh, g_Wkl, n4);
    else if (blockIdx.z == 2) split_body(wv, g_Wvh, g_Wvl, n4);
    else                      split_body(wo, g_Woh, g_Wol, n4);
}

// ---------------------------------------------------------------------------
// HMMA GEMM body (3-MMA bf16 split).
// Block tile 256x128, BK=64; 8 warps = 4(M) x 2(N), each 64x64.
// 2-stage cp.async pipeline, load issued after the chunk barrier.
// ---------------------------------------------------------------------------
#define SA2    72                          // smem row stride (bf16)
#define ATILE2 (256 * SA2 * 2)             // 36864 B (A 256x64 tile)
#define BTILE2 (128 * SA2 * 2)             // 18432 B (B 128x64 tile)
#define STG3   (2 * ATILE2 + 2 * BTILE2)   // 110592 B  (Ah, Al, Bh, Bl)
#define GEMM_SMEM3 (2 * STG3)              // 221184 B
#define BKC2   64
#define NCH2   (DM / BKC2)                 // 16
#define OFF_AH 0
#define OFF_AL ATILE2
#define OFF_BH (2 * ATILE2)
#define OFF_BL (2 * ATILE2 + BTILE2)

template <bool SPLIT_OUT>
__device__ __forceinline__ void gemm64_body(
    const __nv_bfloat16* __restrict__ Ah, const __nv_bfloat16* __restrict__ Al,
    const __nv_bfloat16* __restrict__ Wh, const __nv_bfloat16* __restrict__ Wl,
    const float* __restrict__ bias, float oscale, float* __restrict__ C,
    __nv_bfloat16* __restrict__ Ch, __nv_bfloat16* __restrict__ Cl)
{
    extern __shared__ char smem[];
    const uint32_t sb = smem_to_u32(smem);
    const int tid  = threadIdx.x;
    const int wid  = tid >> 5;
    const int lane = tid & 31;
    const int bm = blockIdx.y * 256;
    const int bn = blockIdx.x * 128;
    const int wm = (wid >> 1) * 64;       // 0,64,128,192
    const int wn = (wid & 1) * 64;        // 0,64

    // A loader: thread t -> row t (256 rows), full 128B row-chunk (8 x cp16)
    const char* gAh = (const char*)(Ah + (size_t)(bm + tid) * DM);
    const char* gAl = (const char*)(Al + (size_t)(bm + tid) * DM);
    const uint32_t soA = (uint32_t)(tid * SA2 * 2);
    // B loader: thread t -> row t>>1 (128 rows), 64B half (4 x cp16)
    const int brow  = tid >> 1;
    const int bhalf = (tid & 1) * 64;
    const char* gBh = (const char*)(Wh + (size_t)(bn + brow) * DM) + bhalf;
    const char* gBl = (const char*)(Wl + (size_t)(bn + brow) * DM) + bhalf;
    const uint32_t soB = (uint32_t)(brow * SA2 * 2) + bhalf;

    auto load_chunk = [&](int c, int stg) {
        const uint32_t base = sb + stg * STG3;
        const int gb = c * (BKC2 * 2);
#pragma unroll
        for (int s = 0; s < 8; s++) {
            CP_ASYNC_16(base + OFF_AH + soA + s * 16, gAh + gb + s * 16);
            CP_ASYNC_16(base + OFF_AL + soA + s * 16, gAl + gb + s * 16);
        }
#pragma unroll
        for (int s = 0; s < 4; s++) {
            CP_ASYNC_16(base + OFF_BH + soB + s * 16, gBh + gb + s * 16);
            CP_ASYNC_16(base + OFF_BL + soB + s * 16, gBl + gb + s * 16);
        }
        CP_ASYNC_COMMIT();
    };

    const int grp = lane >> 3, rin = lane & 7;
    const int a_row = wm + (grp & 1) * 8 + rin;
    const int a_kof = (grp >> 1) * 8;
    const int b_row = wn + (grp >> 1) * 8 + rin;
    const int b_kof = (grp & 1) * 8;

    float acc[4][8][4];
#pragma unroll
    for (int i = 0; i < 4; i++)
#pragma unroll
        for (int j = 0; j < 8; j++)
#pragma unroll
            for (int r = 0; r < 4; r++) acc[i][j][r] = 0.0f;

    load_chunk(0, 0);

    for (int c = 0; c < NCH2; c++) {
        CP_ASYNC_WAIT0();
        __syncthreads();
        if (c + 1 < NCH2) load_chunk(c + 1, (c + 1) & 1);

        const uint32_t base = sb + (c & 1) * STG3;
#pragma unroll
        for (int k0 = 0; k0 < BKC2; k0 += 16) {
            uint32_t ah[4][4], al[4][4];
#pragma unroll
            for (int i = 0; i < 4; i++) {
                uint32_t ad = base + OFF_AH +
                    (uint32_t)((a_row + i * 16) * SA2 + k0 + a_kof) * 2;
                ldsm_x4(ah[i][0], ah[i][1], ah[i][2], ah[i][3], ad);
                ldsm_x4(al[i][0], al[i][1], al[i][2], al[i][3],
                        ad + (OFF_AL - OFF_AH));
            }
            // B in two halves of 4 n8-tiles to cap register pressure
#pragma unroll
            for (int jh = 0; jh < 2; jh++) {
                uint32_t bh[4][2], bl[4][2];
#pragma unroll
                for (int jp = 0; jp < 2; jp++) {
                    uint32_t bd = base + OFF_BH +
                        (uint32_t)((b_row + (jh * 2 + jp) * 16) * SA2 +
                                   k0 + b_kof) * 2;
                    ldsm_x4(bh[jp * 2][0], bh[jp * 2][1],
                            bh[jp * 2 + 1][0], bh[jp * 2 + 1][1], bd);
                    ldsm_x4(bl[jp * 2][0], bl[jp * 2][1],
                            bl[jp * 2 + 1][0], bl[jp * 2 + 1][1],
                            bd + (OFF_BL - OFF_BH));
                }
#pragma unroll
                for (int i = 0; i < 4; i++)
#pragma unroll
                    for (int j = 0; j < 4; j++) {
                        float* a4 = acc[i][jh * 4 + j];
                        mma_bf16(a4, ah[i], bh[j][0], bh[j][1]);
                        mma_bf16(a4, ah[i], bl[j][0], bl[j][1]);
                        mma_bf16(a4, al[i], bh[j][0], bh[j][1]);
                    }
            }
        }
    }

    const int erow = bm + wm + (lane >> 2);
    const int ecol = bn + wn + (lane & 3) * 2;
#pragma unroll
    for (int i = 0; i < 4; i++) {
#pragma unroll
        for (int j = 0; j < 8; j++) {
            const int col = ecol + j * 8;
            const float b0 = bias[col], b1 = bias[col + 1];
            const size_t o0 = (size_t)(erow + i * 16) * DM + col;
            const size_t o1 = (size_t)(erow + i * 16 + 8) * DM + col;
            if (SPLIT_OUT) {
                uint32_t hv, lv;
                split2((acc[i][j][0] + b0) * oscale,
                       (acc[i][j][1] + b1) * oscale, hv, lv);
                *(uint32_t*)(Ch + o0) = hv;
                *(uint32_t*)(Cl + o0) = lv;
                split2((acc[i][j][2] + b0) * oscale,
                       (acc[i][j][3] + b1) * oscale, hv, lv);
                *(uint32_t*)(Ch + o1) = hv;
                *(uint32_t*)(Cl + o1) = lv;
            } else {
                *(float2*)(C + o0) =
                    make_float2(acc[i][j][0] + b0, acc[i][j][1] + b1);
                *(float2*)(C + o1) =
                    make_float2(acc[i][j][2] + b0, acc[i][j][3] + b1);
            }
        }
    }
}

__global__ __launch_bounds__(256, 1) void qkv_gemm64(
    const float* __restrict__ bq, const float* __restrict__ bk,
    const float* __restrict__ bv)
{
    if (blockIdx.z == 0)
        gemm64_body<true>(g_Aqh, g_Aql, g_Wqh, g_Wql, bq, QSCALE,
                          nullptr, g_Qh, g_Ql);
    else if (blockIdx.z == 1)
        gemm64_body<true>(g_Akh, g_Akl, g_Wkh, g_Wkl, bk, 1.0f,
                          nullptr, g_Kh, g_Kl);
    else
        gemm64_body<true>(g_Avh, g_Avl, g_Wvh, g_Wvl, bv, 1.0f,
                          nullptr, g_Vh, g_Vl);
}

__global__ __launch_bounds__(256, 1) void out_gemm64(
    const float* __restrict__ bo, float* __restrict__ out)
{
    gemm64_body<false>(g_Xh, g_Xl, g_Woh, g_Wol, bo, 1.0f,
                       out, nullptr, nullptr);
}

// ---------------------------------------------------------------------------
// HMMA flash attention (unchanged from round 7 best path).
// Q pre-scaled by (1/32)*log2e -> softmax in exp2 domain; Q frags hoisted.
// ---------------------------------------------------------------------------
#define ASA 72
#define ATILE (128 * ASA * 2)
#define A_QH 0
#define A_QL ATILE
#define A_ST0 (2 * ATILE)
#define A_STAGE (4 * ATILE)
#define ATT_SMEM (2 * ATILE + 2 * A_STAGE)   // 184320 B
#define NKT (SS / 128)

__global__ __launch_bounds__(256, 1) void attn_mma(
    const __nv_bfloat16* __restrict__ Qh_, const __nv_bfloat16* __restrict__ Ql_,
    const __nv_bfloat16* __restrict__ Kh_, const __nv_bfloat16* __restrict__ Kl_,
    const __nv_bfloat16* __restrict__ Vh_, const __nv_bfloat16* __restrict__ Vl_,
    __nv_bfloat16* __restrict__ Xh_, __nv_bfloat16* __restrict__ Xl_)
{
    extern __shared__ char smem[];
    const uint32_t sb = smem_to_u32(smem);
    const int tid  = threadIdx.x;
    const int wid  = tid >> 5;
    const int lane = tid & 31;
    const int qm   = wid * 16;
    const int qb = blockIdx.x, h = blockIdx.y, b = blockIdx.z;
    const size_t qrow0 = (size_t)(b * SS + qb * 128);
    const size_t hoff  = (size_t)h * HD;

#pragma unroll
    for (int i = 0; i < 4; i++) {
        int ci = tid + i * 256;
        int r = ci >> 3, cof = (ci & 7) * 16;
        uint32_t so = (uint32_t)(r * ASA * 2) + cof;
        CP_ASYNC_16(sb + A_QH + so,
                    (const char*)(Qh_ + (qrow0 + r) * DM + hoff) + cof);
        CP_ASYNC_16(sb + A_QL + so,
                    (const char*)(Ql_ + (qrow0 + r) * DM + hoff) + cof);
    }
    CP_ASYNC_COMMIT();

    auto load_kv = [&](int kt, int stg) {
        const size_t k0 = (size_t)(b * SS + kt * 128);
        const uint32_t base = sb + A_ST0 + stg * A_STAGE;
#pragma unroll
        for (int i = 0; i < 4; i++) {
            int ci = tid + i * 256;
            int r = ci >> 3, cof = (ci & 7) * 16;
            uint32_t so = (uint32_t)(r * ASA * 2) + cof;
            const size_t g = (k0 + r) * DM + hoff;
            CP_ASYNC_16(base + 0 * ATILE + so, (const char*)(Kh_ + g) + cof);
            CP_ASYNC_16(base + 1 * ATILE + so, (const char*)(Kl_ + g) + cof);
            CP_ASYNC_16(base + 2 * ATILE + so, (const char*)(Vh_ + g) + cof);
            CP_ASYNC_16(base + 3 * ATILE + so, (const char*)(Vl_ + g) + cof);
        }
        CP_ASYNC_COMMIT();
    };

    load_kv(0, 0);

    const int qrow_f = qm + (lane & 7) + ((lane >> 3) & 1) * 8;
    const int qkof_f = ((lane >> 4) & 1) * 8;
    const int krow_f = (lane & 7) + ((lane >> 4) & 1) * 8;
    const int kkof_f = ((lane >> 3) & 1) * 8;
    const int vrow_f = lane & 15;
    const int vcol_f = (lane >> 4) * 8;

    CP_ASYNC_WAIT1();
    __syncthreads();
    uint32_t qfh[4][4], qfl[4][4];
#pragma unroll
    for (int ks = 0; ks < 4; ks++) {
        uint32_t qa = sb + A_QH + (uint32_t)(qrow_f * ASA + qkof_f + ks * 16) * 2;
        ldsm_x4(qfh[ks][0], qfh[ks][1], qfh[ks][2], qfh[ks][3], qa);
        ldsm_x4(qfl[ks][0], qfl[ks][1], qfl[ks][2], qfl[ks][3], qa + ATILE);
    }

    float O[8][4];
#pragma unroll
    for (int jo = 0; jo < 8; jo++)
#pragma unroll
        for (int r = 0; r < 4; r++) O[jo][r] = 0.0f;
    float M0 = -3.0e38f, M1 = -3.0e38f, L0 = 0.0f, L1 = 0.0f;

    for (int kt = 0; kt < NKT; kt++) {
        if (kt + 1 < NKT) {
            load_kv(kt + 1, (kt + 1) & 1);
            CP_ASYNC_WAIT1();
        } else {
            CP_ASYNC_WAIT0();
        }
        __syncthreads();
        const uint32_t stage = sb + A_ST0 + (kt & 1) * A_STAGE;

        float s[16][4];
#pragma unroll
        for (int j = 0; j < 16; j++)
#pragma unroll
            for (int r = 0; r < 4; r++) s[j][r] = 0.0f;

#pragma unroll
        for (int ks = 0; ks < 4; ks++) {
#pragma unroll
            for (int jp = 0; jp < 8; jp++) {
                uint32_t kh[4], kl[4];
                uint32_t ka = stage + 0 * ATILE +
                    (uint32_t)((krow_f + jp * 16) * ASA + kkof_f + ks * 16) * 2;
                ldsm_x4(kh[0], kh[1], kh[2], kh[3], ka);
                ldsm_x4(kl[0], kl[1], kl[2], kl[3], ka + ATILE);
                mma_bf16(s[jp * 2],     qfh[ks], kh[0], kh[1]);
                mma_bf16(s[jp * 2],     qfh[ks], kl[0], kl[1]);
                mma_bf16(s[jp * 2],     qfl[ks], kh[0], kh[1]);
                mma_bf16(s[jp * 2 + 1], qfh[ks], kh[2], kh[3]);
                mma_bf16(s[jp * 2 + 1], qfh[ks], kl[2], kl[3]);
                mma_bf16(s[jp * 2 + 1], qfl[ks], kh[2], kh[3]);
            }
        }

        float mx0 = -3.0e38f, mx1 = -3.0e38f;
#pragma unroll
        for (int j = 0; j < 16; j++) {
            mx0 = fmaxf(mx0, fmaxf(s[j][0], s[j][1]));
            mx1 = fmaxf(mx1, fmaxf(s[j][2], s[j][3]));
        }
        mx0 = fmaxf(mx0, __shfl_xor_sync(0xffffffffu, mx0, 1));
        mx0 = fmaxf(mx0, __shfl_xor_sync(0xffffffffu, mx0, 2));
        mx1 = fmaxf(mx1, __shfl_xor_sync(0xffffffffu, mx1, 1));
        mx1 = fmaxf(mx1, __shfl_xor_sync(0xffffffffu, mx1, 2));

        const float Mn0 = fmaxf(M0, mx0), Mn1 = fmaxf(M1, mx1);
        const float f0 = ex2(M0 - Mn0), f1 = ex2(M1 - Mn1);
        M0 = Mn0; M1 = Mn1;

        float sum0 = 0.0f, sum1 = 0.0f;
#pragma unroll
        for (int j = 0; j < 16; j++) {
            s[j][0] = ex2(s[j][0] - M0);
            s[j][1] = ex2(s[j][1] - M0);
            s[j][2] = ex2(s[j][2] - M1);
            s[j][3] = ex2(s[j][3] - M1);
            sum0 += s[j][0] + s[j][1];
            sum1 += s[j][2] + s[j][3];
        }
        sum0 += __shfl_xor_sync(0xffffffffu, sum0, 1);
        sum0 += __shfl_xor_sync(0xffffffffu, sum0, 2);
        sum1 += __shfl_xor_sync(0xffffffffu, sum1, 1);
        sum1 += __shfl_xor_sync(0xffffffffu, sum1, 2);
        L0 = L0 * f0 + sum0;
        L1 = L1 * f1 + sum1;

#pragma unroll
        for (int jo = 0; jo < 8; jo++) {
            O[jo][0] *= f0; O[jo][1] *= f0;
            O[jo][2] *= f1; O[jo][3] *= f1;
        }

#pragma unroll
        for (int ks2 = 0; ks2 < 8; ks2++) {
            uint32_t ah[4], al[4];
            split2(s[2 * ks2][0],     s[2 * ks2][1],     ah[0], al[0]);
            split2(s[2 * ks2][2],     s[2 * ks2][3],     ah[1], al[1]);
            split2(s[2 * ks2 + 1][0], s[2 * ks2 + 1][1], ah[2], al[2]);
            split2(s[2 * ks2 + 1][2], s[2 * ks2 + 1][3], ah[3], al[3]);
#pragma unroll
            for (int nn = 0; nn < 4; nn++) {
                uint32_t vh[4], vl[4];
                uint32_t va = stage + 2 * ATILE +
                    (uint32_t)((ks2 * 16 + vrow_f) * ASA + nn * 16 + vcol_f) * 2;
                ldsm_x4_t(vh[0], vh[1], vh[2], vh[3], va);
                ldsm_x4_t(vl[0], vl[1], vl[2], vl[3], va + ATILE);
                mma_bf16(O[nn * 2],     ah, vh[0], vh[1]);
                mma_bf16(O[nn * 2],     ah, vl[0], vl[1]);
                mma_bf16(O[nn * 2],     al, vh[0], vh[1]);
                mma_bf16(O[nn * 2 + 1], ah, vh[2], vh[3]);
                mma_bf16(O[nn * 2 + 1], ah, vl[2], vl[3]);
                mma_bf16(O[nn * 2 + 1], al, vh[2], vh[3]);
            }
        }
        __syncthreads();
    }

    const float il0 = 1.0f / L0, il1 = 1.0f / L1;
    const size_t r0 = qrow0 + qm + (lane >> 2);
    const size_t r1 = r0 + 8;
#pragma unroll
    for (int jo = 0; jo < 8; jo++) {
        const size_t col = hoff + jo * 8 + (lane & 3) * 2;
        uint32_t hp, lp;
        split2(O[jo][0] * il0, O[jo][1] * il0, hp, lp);
        *(uint32_t*)(Xh_ + r0 * DM + col) = hp;
        *(uint32_t*)(Xl_ + r0 * DM + col) = lp;
        split2(O[jo][2] * il1, O[jo][3] * il1, hp, lp);
        *(uint32_t*)(Xh_ + r1 * DM + col) = hp;
        *(uint32_t*)(Xl_ + r1 * DM + col) = lp;
    }
}

// ---------------------------------------------------------------------------
extern "C" void kernel_launch(void* const* d_in, const int* in_sizes, int n_in,
                              void* d_out, int out_size)
{
    const float* query = (const float*)d_in[0];
    const float* key   = (const float*)d_in[1];
    const float* value = (const float*)d_in[2];
    const float* Wq    = (const float*)d_in[3];
    const float* bq    = (const float*)d_in[4];
    const float* Wk    = (const float*)d_in[5];
    const float* bk    = (const float*)d_in[6];
    const float* Wv    = (const float*)d_in[7];
    const float* bv    = (const float*)d_in[8];
    const float* Wo    = (const float*)d_in[9];
    const float* bo    = (const float*)d_in[10];
    float* out = (float*)d_out;

    __nv_bfloat16 *qh, *ql, *kh, *kl, *vh, *vl, *xh, *xl;
    cudaGetSymbolAddress((void**)&qh, g_Qh);
    cudaGetSymbolAddress((void**)&ql, g_Ql);
    cudaGetSymbolAddress((void**)&kh, g_Kh);
    cudaGetSymbolAddress((void**)&kl, g_Kl);
    cudaGetSymbolAddress((void**)&vh, g_Vh);
    cudaGetSymbolAddress((void**)&vl, g_Vl);
    cudaGetSymbolAddress((void**)&xh, g_Xh);
    cudaGetSymbolAddress((void**)&xl, g_Xl);

    cudaFuncSetAttribute(qkv_gemm64,
                         cudaFuncAttributeMaxDynamicSharedMemorySize, GEMM_SMEM3);
    cudaFuncSetAttribute(out_gemm64,
                         cudaFuncAttributeMaxDynamicSharedMemorySize, GEMM_SMEM3);
    cudaFuncSetAttribute(attn_mma,
                         cudaFuncAttributeMaxDynamicSharedMemorySize, ATT_SMEM);

    split_inputs_kernel<<<dim3(2048, 1, 3), 256>>>(query, key, value);
    split_weights_kernel<<<dim3(512, 1, 4), 256>>>(Wq, Wk, Wv, Wo);

    qkv_gemm64<<<dim3(DM / 128, MROWS / 256, 3), 256, GEMM_SMEM3>>>(bq, bk, bv);

    attn_mma<<<dim3(SS / 128, HH, BB), 256, ATT_SMEM>>>(qh, ql, kh, kl,
                                                        vh, vl, xh, xl);

    out_gemm64<<<dim3(DM / 128, MROWS / 256), 256, GEMM_SMEM3>>>(bo, out);
}

// round 9
// speedup vs baseline: 1.1250x; 1.1250x over previous
#include <cuda_runtime.h>
#include <cuda_bf16.h>
#include <cuda_fp16.h>
#include <cstdint>

// Problem constants
#define BB 4
#define SS 2048
#define DM 1024
#define HH 16
#define HD 64
#define MROWS (BB * SS)   // 8192

// Q pre-scale: (1/sqrt(D)) * log2(e) folded into Q projection output.
#define QSCALE 0.04508422002778011f

// Scratch (allocation-free rule: __device__ globals)
__device__ __nv_bfloat16 g_Aqh[MROWS * DM], g_Aql[MROWS * DM];
__device__ __nv_bfloat16 g_Akh[MROWS * DM], g_Akl[MROWS * DM];
__device__ __nv_bfloat16 g_Avh[MROWS * DM], g_Avl[MROWS * DM];
__device__ __nv_bfloat16 g_Wqh[DM * DM], g_Wql[DM * DM];
__device__ __nv_bfloat16 g_Wkh[DM * DM], g_Wkl[DM * DM];
__device__ __nv_bfloat16 g_Wvh[DM * DM], g_Wvl[DM * DM];
__device__ __nv_bfloat16 g_Woh[DM * DM], g_Wol[DM * DM];
__device__ __half g_Qf[MROWS * DM];                      // fp16 single (scaled)
__device__ __half g_Kh[MROWS * DM], g_Kl[MROWS * DM];    // fp16 hi/lo
__device__ __half g_Vh[MROWS * DM], g_Vl[MROWS * DM];    // fp16 hi/lo
__device__ __nv_bfloat16 g_Xh[MROWS * DM], g_Xl[MROWS * DM];

// ---------------------------------------------------------------------------
// Portable (sm_80+) tensor-core helpers
// ---------------------------------------------------------------------------
__device__ __forceinline__ uint32_t smem_to_u32(const void* p) {
    uint32_t a;
    asm("{ .reg .u64 t; cvta.to.shared.u64 t, %1; cvt.u32.u64 %0, t; }"
        : "=r"(a) : "l"(p));
    return a;
}

__device__ __forceinline__ void ldsm_x4(uint32_t& r0, uint32_t& r1,
                                        uint32_t& r2, uint32_t& r3,
                                        uint32_t addr) {
    asm volatile("ldmatrix.sync.aligned.m8n8.x4.shared.b16 {%0,%1,%2,%3}, [%4];"
                 : "=r"(r0), "=r"(r1), "=r"(r2), "=r"(r3) : "r"(addr));
}

__device__ __forceinline__ void ldsm_x4_t(uint32_t& r0, uint32_t& r1,
                                          uint32_t& r2, uint32_t& r3,
                                          uint32_t addr) {
    asm volatile("ldmatrix.sync.aligned.m8n8.x4.trans.shared.b16 {%0,%1,%2,%3}, [%4];"
                 : "=r"(r0), "=r"(r1), "=r"(r2), "=r"(r3) : "r"(addr));
}

__device__ __forceinline__ void mma_bf16(float* c, const uint32_t* a,
                                         uint32_t b0, uint32_t b1) {
    asm volatile(
        "mma.sync.aligned.m16n8k16.row.col.f32.bf16.bf16.f32 "
        "{%0,%1,%2,%3}, {%4,%5,%6,%7}, {%8,%9}, {%0,%1,%2,%3};"
        : "+f"(c[0]), "+f"(c[1]), "+f"(c[2]), "+f"(c[3])
        : "r"(a[0]), "r"(a[1]), "r"(a[2]), "r"(a[3]), "r"(b0), "r"(b1));
}

__device__ __forceinline__ void mma_f16(float* c, const uint32_t* a,
                                        uint32_t b0, uint32_t b1) {
    asm volatile(
        "mma.sync.aligned.m16n8k16.row.col.f32.f16.f16.f32 "
        "{%0,%1,%2,%3}, {%4,%5,%6,%7}, {%8,%9}, {%0,%1,%2,%3};"
        : "+f"(c[0]), "+f"(c[1]), "+f"(c[2]), "+f"(c[3])
        : "r"(a[0]), "r"(a[1]), "r"(a[2]), "r"(a[3]), "r"(b0), "r"(b1));
}

__device__ __forceinline__ float ex2(float x) {
    float y;
    asm("ex2.approx.ftz.f32 %0, %1;" : "=f"(y) : "f"(x));
    return y;
}

#define CP_ASYNC_16(smem_u32, gptr) \
    asm volatile("cp.async.cg.shared.global [%0], [%1], 16;" \
        :: "r"(smem_u32), "l"(gptr) : "memory")
#define CP_ASYNC_COMMIT() asm volatile("cp.async.commit_group;" ::: "memory")
#define CP_ASYNC_WAIT1() asm volatile("cp.async.wait_group 1;" ::: "memory")
#define CP_ASYNC_WAIT0() asm volatile("cp.async.wait_group 0;" ::: "memory")

// bf16 hi/lo split, two at a time
__device__ __forceinline__ void split2(float x, float y, uint32_t& hi, uint32_t& lo) {
    __nv_bfloat16 hx = __float2bfloat16_rn(x);
    __nv_bfloat16 hy = __float2bfloat16_rn(y);
    __nv_bfloat16 lx = __float2bfloat16_rn(x - __bfloat162float(hx));
    __nv_bfloat16 ly = __float2bfloat16_rn(y - __bfloat162float(hy));
    hi = ((uint32_t)__bfloat16_as_ushort(hy) << 16) | __bfloat16_as_ushort(hx);
    lo = ((uint32_t)__bfloat16_as_ushort(ly) << 16) | __bfloat16_as_ushort(lx);
}

// fp16 pack (x -> low 16, y -> high 16)
__device__ __forceinline__ uint32_t packh(float x, float y) {
    __half2 h = __floats2half2_rn(x, y);
    return *(uint32_t*)&h;
}

// fp16 hi/lo split, two at a time
__device__ __forceinline__ void splitH2(float x, float y, uint32_t& hi, uint32_t& lo) {
    __half hx = __float2half_rn(x);
    __half hy = __float2half_rn(y);
    __half lx = __float2half_rn(x - __half2float(hx));
    __half ly = __float2half_rn(y - __half2float(hy));
    hi = ((uint32_t)__half_as_ushort(hy) << 16) | __half_as_ushort(hx);
    lo = ((uint32_t)__half_as_ushort(ly) << 16) | __half_as_ushort(lx);
}

__device__ __forceinline__ void split_body(const float* __restrict__ x,
                                           __nv_bfloat16* __restrict__ hi,
                                           __nv_bfloat16* __restrict__ lo, int n4)
{
    int i = blockIdx.x * blockDim.x + threadIdx.x;
    int stride = gridDim.x * blockDim.x;
    for (; i < n4; i += stride) {
        float4 v = ((const float4*)x)[i];
        uint32_t h0, l0, h1, l1;
        split2(v.x, v.y, h0, l0);
        split2(v.z, v.w, h1, l1);
        ((uint2*)hi)[i] = make_uint2(h0, h1);
        ((uint2*)lo)[i] = make_uint2(l0, l1);
    }
}

__global__ __launch_bounds__(256) void split_inputs_kernel(
    const float* __restrict__ q, const float* __restrict__ k,
    const float* __restrict__ v)
{
    const int n4 = MROWS * DM / 4;
    if (blockIdx.z == 0)      split_body(q, g_Aqh, g_Aql, n4);
    else if (blockIdx.z == 1) split_body(k, g_Akh, g_Akl, n4);
    else                      split_body(v, g_Avh, g_Avl, n4);
}

__global__ __launch_bounds__(256) void split_weights_kernel(
    const float* __restrict__ wq, const float* __restrict__ wk,
    const float* __restrict__ wv, const float* __restrict__ wo)
{
    const int n4 = DM * DM / 4;
    if (blockIdx.z == 0)      split_body(wq, g_Wqh, g_Wql, n4);
    else if (blockIdx.z == 1) split_body(wk, g_Wkh, g_Wkl, n4);
    else if (blockIdx.z == 2) split_body(wv, g_Wvh, g_Wvl, n4);
    else                      split_body(wo, g_Woh, g_Wol, n4);
}

// ---------------------------------------------------------------------------
// HMMA GEMM body (bf16 3-MMA split). Block 256x128, BK=64, 8 warps x 64x64.
// OMODE: 0 = fp32 out; 1 = fp16 single (x oscale); 2 = fp16 hi/lo.
// ---------------------------------------------------------------------------
#define SA2    72
#define ATILE2 (256 * SA2 * 2)
#define BTILE2 (128 * SA2 * 2)
#define STG3   (2 * ATILE2 + 2 * BTILE2)   // 110592 B
#define GEMM_SMEM3 (2 * STG3)              // 221184 B
#define BKC2   64
#define NCH2   (DM / BKC2)
#define OFF_AH 0
#define OFF_AL ATILE2
#define OFF_BH (2 * ATILE2)
#define OFF_BL (2 * ATILE2 + BTILE2)

template <int OMODE>
__device__ __forceinline__ void gemm64_body(
    const __nv_bfloat16* __restrict__ Ah, const __nv_bfloat16* __restrict__ Al,
    const __nv_bfloat16* __restrict__ Wh, const __nv_bfloat16* __restrict__ Wl,
    const float* __restrict__ bias, float oscale, float* __restrict__ C,
    void* __restrict__ O0, void* __restrict__ O1)
{
    extern __shared__ char smem[];
    const uint32_t sb = smem_to_u32(smem);
    const int tid  = threadIdx.x;
    const int wid  = tid >> 5;
    const int lane = tid & 31;
    const int bm = blockIdx.y * 256;
    const int bn = blockIdx.x * 128;
    const int wm = (wid >> 1) * 64;
    const int wn = (wid & 1) * 64;

    const char* gAh = (const char*)(Ah + (size_t)(bm + tid) * DM);
    const char* gAl = (const char*)(Al + (size_t)(bm + tid) * DM);
    const uint32_t soA = (uint32_t)(tid * SA2 * 2);
    const int brow  = tid >> 1;
    const int bhalf = (tid & 1) * 64;
    const char* gBh = (const char*)(Wh + (size_t)(bn + brow) * DM) + bhalf;
    const char* gBl = (const char*)(Wl + (size_t)(bn + brow) * DM) + bhalf;
    const uint32_t soB = (uint32_t)(brow * SA2 * 2) + bhalf;

    auto load_chunk = [&](int c, int stg) {
        const uint32_t base = sb + stg * STG3;
        const int gb = c * (BKC2 * 2);
#pragma unroll
        for (int s = 0; s < 8; s++) {
            CP_ASYNC_16(base + OFF_AH + soA + s * 16, gAh + gb + s * 16);
            CP_ASYNC_16(base + OFF_AL + soA + s * 16, gAl + gb + s * 16);
        }
#pragma unroll
        for (int s = 0; s < 4; s++) {
            CP_ASYNC_16(base + OFF_BH + soB + s * 16, gBh + gb + s * 16);
            CP_ASYNC_16(base + OFF_BL + soB + s * 16, gBl + gb + s * 16);
        }
        CP_ASYNC_COMMIT();
    };

    const int grp = lane >> 3, rin = lane & 7;
    const int a_row = wm + (grp & 1) * 8 + rin;
    const int a_kof = (grp >> 1) * 8;
    const int b_row = wn + (grp >> 1) * 8 + rin;
    const int b_kof = (grp & 1) * 8;

    float acc[4][8][4];
#pragma unroll
    for (int i = 0; i < 4; i++)
#pragma unroll
        for (int j = 0; j < 8; j++)
#pragma unroll
            for (int r = 0; r < 4; r++) acc[i][j][r] = 0.0f;

    load_chunk(0, 0);

    for (int c = 0; c < NCH2; c++) {
        CP_ASYNC_WAIT0();
        __syncthreads();
        if (c + 1 < NCH2) load_chunk(c + 1, (c + 1) & 1);

        const uint32_t base = sb + (c & 1) * STG3;
#pragma unroll
        for (int k0 = 0; k0 < BKC2; k0 += 16) {
            uint32_t ah[4][4], al[4][4];
#pragma unroll
            for (int i = 0; i < 4; i++) {
                uint32_t ad = base + OFF_AH +
                    (uint32_t)((a_row + i * 16) * SA2 + k0 + a_kof) * 2;
                ldsm_x4(ah[i][0], ah[i][1], ah[i][2], ah[i][3], ad);
                ldsm_x4(al[i][0], al[i][1], al[i][2], al[i][3],
                        ad + (OFF_AL - OFF_AH));
            }
#pragma unroll
            for (int jh = 0; jh < 2; jh++) {
                uint32_t bh[4][2], bl[4][2];
#pragma unroll
                for (int jp = 0; jp < 2; jp++) {
                    uint32_t bd = base + OFF_BH +
                        (uint32_t)((b_row + (jh * 2 + jp) * 16) * SA2 +
                                   k0 + b_kof) * 2;
                    ldsm_x4(bh[jp * 2][0], bh[jp * 2][1],
                            bh[jp * 2 + 1][0], bh[jp * 2 + 1][1], bd);
                    ldsm_x4(bl[jp * 2][0], bl[jp * 2][1],
                            bl[jp * 2 + 1][0], bl[jp * 2 + 1][1],
                            bd + (OFF_BL - OFF_BH));
                }
#pragma unroll
                for (int i = 0; i < 4; i++)
#pragma unroll
                    for (int j = 0; j < 4; j++) {
                        float* a4 = acc[i][jh * 4 + j];
                        mma_bf16(a4, ah[i], bh[j][0], bh[j][1]);
                        mma_bf16(a4, ah[i], bl[j][0], bl[j][1]);
                        mma_bf16(a4, al[i], bh[j][0], bh[j][1]);
                    }
            }
        }
    }

    const int erow = bm + wm + (lane >> 2);
    const int ecol = bn + wn + (lane & 3) * 2;
#pragma unroll
    for (int i = 0; i < 4; i++) {
#pragma unroll
        for (int j = 0; j < 8; j++) {
            const int col = ecol + j * 8;
            const float b0 = bias[col], b1 = bias[col + 1];
            const size_t o0 = (size_t)(erow + i * 16) * DM + col;
            const size_t o1 = (size_t)(erow + i * 16 + 8) * DM + col;
            const float c0 = (acc[i][j][0] + b0) * oscale;
            const float c1 = (acc[i][j][1] + b1) * oscale;
            const float c2 = (acc[i][j][2] + b0) * oscale;
            const float c3 = (acc[i][j][3] + b1) * oscale;
            if (OMODE == 0) {
                *(float2*)(C + o0) = make_float2(c0, c1);
                *(float2*)(C + o1) = make_float2(c2, c3);
            } else if (OMODE == 1) {
                __half* Qf = (__half*)O0;
                *(uint32_t*)(Qf + o0) = packh(c0, c1);
                *(uint32_t*)(Qf + o1) = packh(c2, c3);
            } else {
                __half* Hh = (__half*)O0;
                __half* Hl = (__half*)O1;
                uint32_t hv, lv;
                splitH2(c0, c1, hv, lv);
                *(uint32_t*)(Hh + o0) = hv;
                *(uint32_t*)(Hl + o0) = lv;
                splitH2(c2, c3, hv, lv);
                *(uint32_t*)(Hh + o1) = hv;
                *(uint32_t*)(Hl + o1) = lv;
            }
        }
    }
}

__global__ __launch_bounds__(256, 1) void qkv_gemm64(
    const float* __restrict__ bq, const float* __restrict__ bk,
    const float* __restrict__ bv)
{
    if (blockIdx.z == 0)
        gemm64_body<1>(g_Aqh, g_Aql, g_Wqh, g_Wql, bq, QSCALE,
                       nullptr, g_Qf, nullptr);
    else if (blockIdx.z == 1)
        gemm64_body<2>(g_Akh, g_Akl, g_Wkh, g_Wkl, bk, 1.0f,
                       nullptr, g_Kh, g_Kl);
    else
        gemm64_body<2>(g_Avh, g_Avl, g_Wvh, g_Wvl, bv, 1.0f,
                       nullptr, g_Vh, g_Vl);
}

__global__ __launch_bounds__(256, 1) void out_gemm64(
    const float* __restrict__ bo, float* __restrict__ out)
{
    gemm64_body<0>(g_Xh, g_Xl, g_Woh, g_Wol, bo, 1.0f,
                   out, nullptr, nullptr);
}

// ---------------------------------------------------------------------------
// HMMA flash attention, fp16 2-MMA scheme.
// Q: single fp16 (pre-scaled, exp2 domain). K,V: fp16 hi/lo.
// S = Qf@(Kh+Kl)  (2 MMAs);  O += Pf@(Vh+Vl)  (2 MMAs).
// ---------------------------------------------------------------------------
#define ASA 72
#define ATILE (128 * ASA * 2)
#define A_QF 0
#define A_ST0 ATILE
#define A_STAGE (4 * ATILE)                 // Kh, Kl, Vh, Vl
#define ATT_SMEM (ATILE + 2 * A_STAGE)      // 165888 B
#define NKT (SS / 128)

__global__ __launch_bounds__(256, 1) void attn_mma(
    const __half* __restrict__ Qf_,
    const __half* __restrict__ Kh_, const __half* __restrict__ Kl_,
    const __half* __restrict__ Vh_, const __half* __restrict__ Vl_,
    __nv_bfloat16* __restrict__ Xh_, __nv_bfloat16* __restrict__ Xl_)
{
    extern __shared__ char smem[];
    const uint32_t sb = smem_to_u32(smem);
    const int tid  = threadIdx.x;
    const int wid  = tid >> 5;
    const int lane = tid & 31;
    const int qm   = wid * 16;
    const int qb = blockIdx.x, h = blockIdx.y, b = blockIdx.z;
    const size_t qrow0 = (size_t)(b * SS + qb * 128);
    const size_t hoff  = (size_t)h * HD;

    // Q tile (single fp16) via cp.async (group 0)
#pragma unroll
    for (int i = 0; i < 4; i++) {
        int ci = tid + i * 256;
        int r = ci >> 3, cof = (ci & 7) * 16;
        uint32_t so = (uint32_t)(r * ASA * 2) + cof;
        CP_ASYNC_16(sb + A_QF + so,
                    (const char*)(Qf_ + (qrow0 + r) * DM + hoff) + cof);
    }
    CP_ASYNC_COMMIT();

    auto load_kv = [&](int kt, int stg) {
        const size_t k0 = (size_t)(b * SS + kt * 128);
        const uint32_t base = sb + A_ST0 + stg * A_STAGE;
#pragma unroll
        for (int i = 0; i < 4; i++) {
            int ci = tid + i * 256;
            int r = ci >> 3, cof = (ci & 7) * 16;
            uint32_t so = (uint32_t)(r * ASA * 2) + cof;
            const size_t g = (k0 + r) * DM + hoff;
            CP_ASYNC_16(base + 0 * ATILE + so, (const char*)(Kh_ + g) + cof);
            CP_ASYNC_16(base + 1 * ATILE + so, (const char*)(Kl_ + g) + cof);
            CP_ASYNC_16(base + 2 * ATILE + so, (const char*)(Vh_ + g) + cof);
            CP_ASYNC_16(base + 3 * ATILE + so, (const char*)(Vl_ + g) + cof);
        }
        CP_ASYNC_COMMIT();
    };

    load_kv(0, 0);    // group 1

    const int qrow_f = qm + (lane & 7) + ((lane >> 3) & 1) * 8;
    const int qkof_f = ((lane >> 4) & 1) * 8;
    const int krow_f = (lane & 7) + ((lane >> 4) & 1) * 8;
    const int kkof_f = ((lane >> 3) & 1) * 8;
    const int vrow_f = lane & 15;
    const int vcol_f = (lane >> 4) * 8;

    // Hoist Q fragments (Q group done after WAIT1)
    CP_ASYNC_WAIT1();
    __syncthreads();
    uint32_t qf[4][4];
#pragma unroll
    for (int ks = 0; ks < 4; ks++) {
        uint32_t qa = sb + A_QF + (uint32_t)(qrow_f * ASA + qkof_f + ks * 16) * 2;
        ldsm_x4(qf[ks][0], qf[ks][1], qf[ks][2], qf[ks][3], qa);
    }

    float O[8][4];
#pragma unroll
    for (int jo = 0; jo < 8; jo++)
#pragma unroll
        for (int r = 0; r < 4; r++) O[jo][r] = 0.0f;
    float M0 = -3.0e38f, M1 = -3.0e38f, L0 = 0.0f, L1 = 0.0f;

    for (int kt = 0; kt < NKT; kt++) {
        if (kt + 1 < NKT) {
            load_kv(kt + 1, (kt + 1) & 1);
            CP_ASYNC_WAIT1();
        } else {
            CP_ASYNC_WAIT0();
        }
        __syncthreads();
        const uint32_t stage = sb + A_ST0 + (kt & 1) * A_STAGE;

        // ---- S = Qf @ (Kh + Kl)^T  (2 MMAs per n8-pair) ----
        float s[16][4];
#pragma unroll
        for (int j = 0; j < 16; j++)
#pragma unroll
            for (int r = 0; r < 4; r++) s[j][r] = 0.0f;

#pragma unroll
        for (int ks = 0; ks < 4; ks++) {
#pragma unroll
            for (int jp = 0; jp < 8; jp++) {
                uint32_t kh[4], kl[4];
                uint32_t ka = stage + 0 * ATILE +
                    (uint32_t)((krow_f + jp * 16) * ASA + kkof_f + ks * 16) * 2;
                ldsm_x4(kh[0], kh[1], kh[2], kh[3], ka);
                ldsm_x4(kl[0], kl[1], kl[2], kl[3], ka + ATILE);
                mma_f16(s[jp * 2],     qf[ks], kh[0], kh[1]);
                mma_f16(s[jp * 2],     qf[ks], kl[0], kl[1]);
                mma_f16(s[jp * 2 + 1], qf[ks], kh[2], kh[3]);
                mma_f16(s[jp * 2 + 1], qf[ks], kl[2], kl[3]);
            }
        }

        // ---- online softmax (exp2 domain) ----
        float mx0 = -3.0e38f, mx1 = -3.0e38f;
#pragma unroll
        for (int j = 0; j < 16; j++) {
            mx0 = fmaxf(mx0, fmaxf(s[j][0], s[j][1]));
            mx1 = fmaxf(mx1, fmaxf(s[j][2], s[j][3]));
        }
        mx0 = fmaxf(mx0, __shfl_xor_sync(0xffffffffu, mx0, 1));
        mx0 = fmaxf(mx0, __shfl_xor_sync(0xffffffffu, mx0, 2));
        mx1 = fmaxf(mx1, __shfl_xor_sync(0xffffffffu, mx1, 1));
        mx1 = fmaxf(mx1, __shfl_xor_sync(0xffffffffu, mx1, 2));

        const float Mn0 = fmaxf(M0, mx0), Mn1 = fmaxf(M1, mx1);
        const float f0 = ex2(M0 - Mn0), f1 = ex2(M1 - Mn1);
        M0 = Mn0; M1 = Mn1;

        float sum0 = 0.0f, sum1 = 0.0f;
#pragma unroll
        for (int j = 0; j < 16; j++) {
            s[j][0] = ex2(s[j][0] - M0);
            s[j][1] = ex2(s[j][1] - M0);
            s[j][2] = ex2(s[j][2] - M1);
            s[j][3] = ex2(s[j][3] - M1);
            sum0 += s[j][0] + s[j][1];
            sum1 += s[j][2] + s[j][3];
        }
        sum0 += __shfl_xor_sync(0xffffffffu, sum0, 1);
        sum0 += __shfl_xor_sync(0xffffffffu, sum0, 2);
        sum1 += __shfl_xor_sync(0xffffffffu, sum1, 1);
        sum1 += __shfl_xor_sync(0xffffffffu, sum1, 2);
        L0 = L0 * f0 + sum0;
        L1 = L1 * f1 + sum1;

#pragma unroll
        for (int jo = 0; jo < 8; jo++) {
            O[jo][0] *= f0; O[jo][1] *= f0;
            O[jo][2] *= f1; O[jo][3] *= f1;
        }

        // ---- O += Pf @ (Vh + Vl)  (2 MMAs per n8-pair) ----
#pragma unroll
        for (int ks2 = 0; ks2 < 8; ks2++) {
            uint32_t ph[4];
            ph[0] = packh(s[2 * ks2][0],     s[2 * ks2][1]);
            ph[1] = packh(s[2 * ks2][2],     s[2 * ks2][3]);
            ph[2] = packh(s[2 * ks2 + 1][0], s[2 * ks2 + 1][1]);
            ph[3] = packh(s[2 * ks2 + 1][2], s[2 * ks2 + 1][3]);
#pragma unroll
            for (int nn = 0; nn < 4; nn++) {
                uint32_t vh[4], vl[4];
                uint32_t va = stage + 2 * ATILE +
                    (uint32_t)((ks2 * 16 + vrow_f) * ASA + nn * 16 + vcol_f) * 2;
                ldsm_x4_t(vh[0], vh[1], vh[2], vh[3], va);
                ldsm_x4_t(vl[0], vl[1], vl[2], vl[3], va + ATILE);
                mma_f16(O[nn * 2],     ph, vh[0], vh[1]);
                mma_f16(O[nn * 2],     ph, vl[0], vl[1]);
                mma_f16(O[nn * 2 + 1], ph, vh[2], vh[3]);
                mma_f16(O[nn * 2 + 1], ph, vl[2], vl[3]);
            }
        }
        __syncthreads();
    }

    // ---- epilogue: normalize, bf16 hi/lo split for out projection ----
    const float il0 = 1.0f / L0, il1 = 1.0f / L1;
    const size_t r0 = qrow0 + qm + (lane >> 2);
    const size_t r1 = r0 + 8;
#pragma unroll
    for (int jo = 0; jo < 8; jo++) {
        const size_t col = hoff + jo * 8 + (lane & 3) * 2;
        uint32_t hp, lp;
        split2(O[jo][0] * il0, O[jo][1] * il0, hp, lp);
        *(uint32_t*)(Xh_ + r0 * DM + col) = hp;
        *(uint32_t*)(Xl_ + r0 * DM + col) = lp;
        split2(O[jo][2] * il1, O[jo][3] * il1, hp, lp);
        *(uint32_t*)(Xh_ + r1 * DM + col) = hp;
        *(uint32_t*)(Xl_ + r1 * DM + col) = lp;
    }
}

// ---------------------------------------------------------------------------
extern "C" void kernel_launch(void* const* d_in, const int* in_sizes, int n_in,
                              void* d_out, int out_size)
{
    const float* query = (const float*)d_in[0];
    const float* key   = (const float*)d_in[1];
    const float* value = (const float*)d_in[2];
    const float* Wq    = (const float*)d_in[3];
    const float* bq    = (const float*)d_in[4];
    const float* Wk    = (const float*)d_in[5];
    const float* bk    = (const float*)d_in[6];
    const float* Wv    = (const float*)d_in[7];
    const float* bv    = (const float*)d_in[8];
    const float* Wo    = (const float*)d_in[9];
    const float* bo    = (const float*)d_in[10];
    float* out = (float*)d_out;

    __half *qf, *kh, *kl, *vh, *vl;
    __nv_bfloat16 *xh, *xl;
    cudaGetSymbolAddress((void**)&qf, g_Qf);
    cudaGetSymbolAddress((void**)&kh, g_Kh);
    cudaGetSymbolAddress((void**)&kl, g_Kl);
    cudaGetSymbolAddress((void**)&vh, g_Vh);
    cudaGetSymbolAddress((void**)&vl, g_Vl);
    cudaGetSymbolAddress((void**)&xh, g_Xh);
    cudaGetSymbolAddress((void**)&xl, g_Xl);

    cudaFuncSetAttribute(qkv_gemm64,
                         cudaFuncAttributeMaxDynamicSharedMemorySize, GEMM_SMEM3);
    cudaFuncSetAttribute(out_gemm64,
                         cudaFuncAttributeMaxDynamicSharedMemorySize, GEMM_SMEM3);
    cudaFuncSetAttribute(attn_mma,
                         cudaFuncAttributeMaxDynamicSharedMemorySize, ATT_SMEM);

    split_inputs_kernel<<<dim3(2048, 1, 3), 256>>>(query, key, value);
    split_weights_kernel<<<dim3(512, 1, 4), 256>>>(Wq, Wk, Wv, Wo);

    qkv_gemm64<<<dim3(DM / 128, MROWS / 256, 3), 256, GEMM_SMEM3>>>(bq, bk, bv);

    attn_mma<<<dim3(SS / 128, HH, BB), 256, ATT_SMEM>>>(qf, kh, kl,
                                                        vh, vl, xh, xl);

    out_gemm64<<<dim3(DM / 128, MROWS / 256), 256, GEMM_SMEM3>>>(bo, out);
}

// round 10
// speedup vs baseline: 1.3210x; 1.1741x over previous
#include <cuda_runtime.h>
#include <cuda_bf16.h>
#include <cuda_fp16.h>
#include <cstdint>

// Problem constants
#define BB 4
#define SS 2048
#define DM 1024
#define HH 16
#define HD 64
#define MROWS (BB * SS)   // 8192

// Q pre-scale: (1/sqrt(D)) * log2(e) folded into Q projection output.
#define QSCALE 0.04508422002778011f

// Scratch (allocation-free rule: __device__ globals)
__device__ __half g_Aqh[MROWS * DM], g_Aql[MROWS * DM];   // split(query) fp16
__device__ __half g_Akh[MROWS * DM], g_Akl[MROWS * DM];   // split(key)
__device__ __half g_Avh[MROWS * DM], g_Avl[MROWS * DM];   // split(value)
__device__ __half g_Wqf[DM * DM], g_Wkf[DM * DM];         // weights single fp16
__device__ __half g_Wvf[DM * DM], g_Wof[DM * DM];
__device__ __half g_Qf[MROWS * DM];                       // fp16 single (scaled)
__device__ __half g_Kh[MROWS * DM], g_Kl[MROWS * DM];     // fp16 hi/lo
__device__ __half g_Vh[MROWS * DM], g_Vl[MROWS * DM];     // fp16 hi/lo
__device__ __half g_Xh[MROWS * DM], g_Xl[MROWS * DM];     // attention out hi/lo

// ---------------------------------------------------------------------------
// Portable (sm_80+) tensor-core helpers
// ---------------------------------------------------------------------------
__device__ __forceinline__ uint32_t smem_to_u32(const void* p) {
    uint32_t a;
    asm("{ .reg .u64 t; cvta.to.shared.u64 t, %1; cvt.u32.u64 %0, t; }"
        : "=r"(a) : "l"(p));
    return a;
}

__device__ __forceinline__ void ldsm_x4(uint32_t& r0, uint32_t& r1,
                                        uint32_t& r2, uint32_t& r3,
                                        uint32_t addr) {
    asm volatile("ldmatrix.sync.aligned.m8n8.x4.shared.b16 {%0,%1,%2,%3}, [%4];"
                 : "=r"(r0), "=r"(r1), "=r"(r2), "=r"(r3) : "r"(addr));
}

__device__ __forceinline__ void ldsm_x4_t(uint32_t& r0, uint32_t& r1,
                                          uint32_t& r2, uint32_t& r3,
                                          uint32_t addr) {
    asm volatile("ldmatrix.sync.aligned.m8n8.x4.trans.shared.b16 {%0,%1,%2,%3}, [%4];"
                 : "=r"(r0), "=r"(r1), "=r"(r2), "=r"(r3) : "r"(addr));
}

__device__ __forceinline__ void mma_f16(float* c, const uint32_t* a,
                                        uint32_t b0, uint32_t b1) {
    asm volatile(
        "mma.sync.aligned.m16n8k16.row.col.f32.f16.f16.f32 "
        "{%0,%1,%2,%3}, {%4,%5,%6,%7}, {%8,%9}, {%0,%1,%2,%3};"
        : "+f"(c[0]), "+f"(c[1]), "+f"(c[2]), "+f"(c[3])
        : "r"(a[0]), "r"(a[1]), "r"(a[2]), "r"(a[3]), "r"(b0), "r"(b1));
}

__device__ __forceinline__ float ex2(float x) {
    float y;
    asm("ex2.approx.ftz.f32 %0, %1;" : "=f"(y) : "f"(x));
    return y;
}

#define CP_ASYNC_16(smem_u32, gptr) \
    asm volatile("cp.async.cg.shared.global [%0], [%1], 16;" \
        :: "r"(smem_u32), "l"(gptr) : "memory")
#define CP_ASYNC_COMMIT() asm volatile("cp.async.commit_group;" ::: "memory")
#define CP_ASYNC_WAIT1() asm volatile("cp.async.wait_group 1;" ::: "memory")
#define CP_ASYNC_WAIT0() asm volatile("cp.async.wait_group 0;" ::: "memory")

// fp16 pack (x -> low 16, y -> high 16)
__device__ __forceinline__ uint32_t packh(float x, float y) {
    __half2 h = __floats2half2_rn(x, y);
    return *(uint32_t*)&h;
}

// fp16 hi/lo split, two at a time
__device__ __forceinline__ void splitH2(float x, float y, uint32_t& hi, uint32_t& lo) {
    __half hx = __float2half_rn(x);
    __half hy = __float2half_rn(y);
    __half lx = __float2half_rn(x - __half2float(hx));
    __half ly = __float2half_rn(y - __half2float(hy));
    hi = ((uint32_t)__half_as_ushort(hy) << 16) | __half_as_ushort(hx);
    lo = ((uint32_t)__half_as_ushort(ly) << 16) | __half_as_ushort(lx);
}

// fp32 -> fp16 hi/lo split (inputs; A-side effectively exact)
__device__ __forceinline__ void split_body_hl(const float* __restrict__ x,
                                              __half* __restrict__ hi,
                                              __half* __restrict__ lo, int n4)
{
    int i = blockIdx.x * blockDim.x + threadIdx.x;
    int stride = gridDim.x * blockDim.x;
    for (; i < n4; i += stride) {
        float4 v = ((const float4*)x)[i];
        uint32_t h0, l0, h1, l1;
        splitH2(v.x, v.y, h0, l0);
        splitH2(v.z, v.w, h1, l1);
        ((uint2*)hi)[i] = make_uint2(h0, h1);
        ((uint2*)lo)[i] = make_uint2(l0, l1);
    }
}

// fp32 -> single fp16 (weights)
__device__ __forceinline__ void split_body_f(const float* __restrict__ x,
                                             __half* __restrict__ f, int n4)
{
    int i = blockIdx.x * blockDim.x + threadIdx.x;
    int stride = gridDim.x * blockDim.x;
    for (; i < n4; i += stride) {
        float4 v = ((const float4*)x)[i];
        ((uint2*)f)[i] = make_uint2(packh(v.x, v.y), packh(v.z, v.w));
    }
}

__global__ __launch_bounds__(256) void split_inputs_kernel(
    const float* __restrict__ q, const float* __restrict__ k,
    const float* __restrict__ v)
{
    const int n4 = MROWS * DM / 4;
    if (blockIdx.z == 0)      split_body_hl(q, g_Aqh, g_Aql, n4);
    else if (blockIdx.z == 1) split_body_hl(k, g_Akh, g_Akl, n4);
    else                      split_body_hl(v, g_Avh, g_Avl, n4);
}

__global__ __launch_bounds__(256) void split_weights_kernel(
    const float* __restrict__ wq, const float* __restrict__ wk,
    const float* __restrict__ wv, const float* __restrict__ wo)
{
    const int n4 = DM * DM / 4;
    if (blockIdx.z == 0)      split_body_f(wq, g_Wqf, n4);
    else if (blockIdx.z == 1) split_body_f(wk, g_Wkf, n4);
    else if (blockIdx.z == 2) split_body_f(wv, g_Wvf, n4);
    else                      split_body_f(wo, g_Wof, n4);
}

// ---------------------------------------------------------------------------
// HMMA GEMM body, fp16 2-MMA scheme: C = (Ah+Al) @ Wf^T + bias.
// Block 256x128, BK=64, 8 warps x 64x64, 2-stage cp.async pipeline.
// OMODE: 0 = fp32 out; 1 = fp16 single (x oscale); 2 = fp16 hi/lo.
// ---------------------------------------------------------------------------
#define SA2    72
#define ATILE2 (256 * SA2 * 2)             // 36864 B (A 256x64 tile)
#define BTILE2 (128 * SA2 * 2)             // 18432 B (W 128x64 tile)
#define STG3   (2 * ATILE2 + BTILE2)       // 92160 B  (Ah, Al, Wf)
#define GEMM_SMEM3 (2 * STG3)              // 184320 B
#define BKC2   64
#define NCH2   (DM / BKC2)                 // 16
#define OFF_AH 0
#define OFF_AL ATILE2
#define OFF_WF (2 * ATILE2)

template <int OMODE>
__device__ __forceinline__ void gemm64_body(
    const __half* __restrict__ Ah, const __half* __restrict__ Al,
    const __half* __restrict__ Wf,
    const float* __restrict__ bias, float oscale, float* __restrict__ C,
    void* __restrict__ O0, void* __restrict__ O1)
{
    extern __shared__ char smem[];
    const uint32_t sb = smem_to_u32(smem);
    const int tid  = threadIdx.x;
    const int wid  = tid >> 5;
    const int lane = tid & 31;
    const int bm = blockIdx.y * 256;
    const int bn = blockIdx.x * 128;
    const int wm = (wid >> 1) * 64;
    const int wn = (wid & 1) * 64;

    // A loader: thread t -> row t, full 128B row-chunk (8 x cp16)
    const char* gAh = (const char*)(Ah + (size_t)(bm + tid) * DM);
    const char* gAl = (const char*)(Al + (size_t)(bm + tid) * DM);
    const uint32_t soA = (uint32_t)(tid * SA2 * 2);
    // W loader: thread t -> row t>>1, 64B half (4 x cp16)
    const int brow  = tid >> 1;
    const int bhalf = (tid & 1) * 64;
    const char* gWf = (const char*)(Wf + (size_t)(bn + brow) * DM) + bhalf;
    const uint32_t soB = (uint32_t)(brow * SA2 * 2) + bhalf;

    auto load_chunk = [&](int c, int stg) {
        const uint32_t base = sb + stg * STG3;
        const int gb = c * (BKC2 * 2);
#pragma unroll
        for (int s = 0; s < 8; s++) {
            CP_ASYNC_16(base + OFF_AH + soA + s * 16, gAh + gb + s * 16);
            CP_ASYNC_16(base + OFF_AL + soA + s * 16, gAl + gb + s * 16);
        }
#pragma unroll
        for (int s = 0; s < 4; s++)
            CP_ASYNC_16(base + OFF_WF + soB + s * 16, gWf + gb + s * 16);
        CP_ASYNC_COMMIT();
    };

    const int grp = lane >> 3, rin = lane & 7;
    const int a_row = wm + (grp & 1) * 8 + rin;
    const int a_kof = (grp >> 1) * 8;
    const int b_row = wn + (grp >> 1) * 8 + rin;
    const int b_kof = (grp & 1) * 8;

    float acc[4][8][4];
#pragma unroll
    for (int i = 0; i < 4; i++)
#pragma unroll
        for (int j = 0; j < 8; j++)
#pragma unroll
            for (int r = 0; r < 4; r++) acc[i][j][r] = 0.0f;

    load_chunk(0, 0);

    for (int c = 0; c < NCH2; c++) {
        CP_ASYNC_WAIT0();
        __syncthreads();
        if (c + 1 < NCH2) load_chunk(c + 1, (c + 1) & 1);

        const uint32_t base = sb + (c & 1) * STG3;
#pragma unroll
        for (int k0 = 0; k0 < BKC2; k0 += 16) {
            uint32_t ah[4][4], al[4][4];
#pragma unroll
            for (int i = 0; i < 4; i++) {
                uint32_t ad = base + OFF_AH +
                    (uint32_t)((a_row + i * 16) * SA2 + k0 + a_kof) * 2;
                ldsm_x4(ah[i][0], ah[i][1], ah[i][2], ah[i][3], ad);
                ldsm_x4(al[i][0], al[i][1], al[i][2], al[i][3],
                        ad + (OFF_AL - OFF_AH));
            }
            uint32_t wf[8][2];
#pragma unroll
            for (int jp = 0; jp < 4; jp++) {
                uint32_t bd = base + OFF_WF +
                    (uint32_t)((b_row + jp * 16) * SA2 + k0 + b_kof) * 2;
                ldsm_x4(wf[jp * 2][0], wf[jp * 2][1],
                        wf[jp * 2 + 1][0], wf[jp * 2 + 1][1], bd);
            }
#pragma unroll
            for (int i = 0; i < 4; i++)
#pragma unroll
                for (int j = 0; j < 8; j++) {
                    float* a4 = acc[i][j];
                    mma_f16(a4, ah[i], wf[j][0], wf[j][1]);
                    mma_f16(a4, al[i], wf[j][0], wf[j][1]);
                }
        }
    }

    const int erow = bm + wm + (lane >> 2);
    const int ecol = bn + wn + (lane & 3) * 2;
#pragma unroll
    for (int i = 0; i < 4; i++) {
#pragma unroll
        for (int j = 0; j < 8; j++) {
            const int col = ecol + j * 8;
            const float b0 = bias[col], b1 = bias[col + 1];
            const size_t o0 = (size_t)(erow + i * 16) * DM + col;
            const size_t o1 = (size_t)(erow + i * 16 + 8) * DM + col;
            const float c0 = (acc[i][j][0] + b0) * oscale;
            const float c1 = (acc[i][j][1] + b1) * oscale;
            const float c2 = (acc[i][j][2] + b0) * oscale;
            const float c3 = (acc[i][j][3] + b1) * oscale;
            if (OMODE == 0) {
                *(float2*)(C + o0) = make_float2(c0, c1);
                *(float2*)(C + o1) = make_float2(c2, c3);
            } else if (OMODE == 1) {
                __half* Qf = (__half*)O0;
                *(uint32_t*)(Qf + o0) = packh(c0, c1);
                *(uint32_t*)(Qf + o1) = packh(c2, c3);
            } else {
                __half* Hh = (__half*)O0;
                __half* Hl = (__half*)O1;
                uint32_t hv, lv;
                splitH2(c0, c1, hv, lv);
                *(uint32_t*)(Hh + o0) = hv;
                *(uint32_t*)(Hl + o0) = lv;
                splitH2(c2, c3, hv, lv);
                *(uint32_t*)(Hh + o1) = hv;
                *(uint32_t*)(Hl + o1) = lv;
            }
        }
    }
}

__global__ __launch_bounds__(256, 1) void qkv_gemm64(
    const float* __restrict__ bq, const float* __restrict__ bk,
    const float* __restrict__ bv)
{
    if (blockIdx.z == 0)
        gemm64_body<1>(g_Aqh, g_Aql, g_Wqf, bq, QSCALE, nullptr, g_Qf, nullptr);
    else if (blockIdx.z == 1)
        gemm64_body<2>(g_Akh, g_Akl, g_Wkf, bk, 1.0f, nullptr, g_Kh, g_Kl);
    else
        gemm64_body<2>(g_Avh, g_Avl, g_Wvf, bv, 1.0f, nullptr, g_Vh, g_Vl);
}

__global__ __launch_bounds__(256, 1) void out_gemm64(
    const float* __restrict__ bo, float* __restrict__ out)
{
    gemm64_body<0>(g_Xh, g_Xl, g_Wof, bo, 1.0f, out, nullptr, nullptr);
}

// ---------------------------------------------------------------------------
// HMMA flash attention, fp16 2-MMA scheme (round 9 validated path).
// Q: single fp16 (pre-scaled, exp2 domain). K,V: fp16 hi/lo.
// ---------------------------------------------------------------------------
#define ASA 72
#define ATILE (128 * ASA * 2)
#define A_QF 0
#define A_ST0 ATILE
#define A_STAGE (4 * ATILE)                 // Kh, Kl, Vh, Vl
#define ATT_SMEM (ATILE + 2 * A_STAGE)      // 165888 B
#define NKT (SS / 128)

__global__ __launch_bounds__(256, 1) void attn_mma(
    const __half* __restrict__ Qf_,
    const __half* __restrict__ Kh_, const __half* __restrict__ Kl_,
    const __half* __restrict__ Vh_, const __half* __restrict__ Vl_,
    __half* __restrict__ Xh_, __half* __restrict__ Xl_)
{
    extern __shared__ char smem[];
    const uint32_t sb = smem_to_u32(smem);
    const int tid  = threadIdx.x;
    const int wid  = tid >> 5;
    const int lane = tid & 31;
    const int qm   = wid * 16;
    const int qb = blockIdx.x, h = blockIdx.y, b = blockIdx.z;
    const size_t qrow0 = (size_t)(b * SS + qb * 128);
    const size_t hoff  = (size_t)h * HD;

    // Q tile (single fp16) via cp.async (group 0)
#pragma unroll
    for (int i = 0; i < 4; i++) {
        int ci = tid + i * 256;
        int r = ci >> 3, cof = (ci & 7) * 16;
        uint32_t so = (uint32_t)(r * ASA * 2) + cof;
        CP_ASYNC_16(sb + A_QF + so,
                    (const char*)(Qf_ + (qrow0 + r) * DM + hoff) + cof);
    }
    CP_ASYNC_COMMIT();

    auto load_kv = [&](int kt, int stg) {
        const size_t k0 = (size_t)(b * SS + kt * 128);
        const uint32_t base = sb + A_ST0 + stg * A_STAGE;
#pragma unroll
        for (int i = 0; i < 4; i++) {
            int ci = tid + i * 256;
            int r = ci >> 3, cof = (ci & 7) * 16;
            uint32_t so = (uint32_t)(r * ASA * 2) + cof;
            const size_t g = (k0 + r) * DM + hoff;
            CP_ASYNC_16(base + 0 * ATILE + so, (const char*)(Kh_ + g) + cof);
            CP_ASYNC_16(base + 1 * ATILE + so, (const char*)(Kl_ + g) + cof);
            CP_ASYNC_16(base + 2 * ATILE + so, (const char*)(Vh_ + g) + cof);
            CP_ASYNC_16(base + 3 * ATILE + so, (const char*)(Vl_ + g) + cof);
        }
        CP_ASYNC_COMMIT();
    };

    load_kv(0, 0);    // group 1

    const int qrow_f = qm + (lane & 7) + ((lane >> 3) & 1) * 8;
    const int qkof_f = ((lane >> 4) & 1) * 8;
    const int krow_f = (lane & 7) + ((lane >> 4) & 1) * 8;
    const int kkof_f = ((lane >> 3) & 1) * 8;
    const int vrow_f = lane & 15;
    const int vcol_f = (lane >> 4) * 8;

    // Hoist Q fragments (Q group done after WAIT1)
    CP_ASYNC_WAIT1();
    __syncthreads();
    uint32_t qf[4][4];
#pragma unroll
    for (int ks = 0; ks < 4; ks++) {
        uint32_t qa = sb + A_QF + (uint32_t)(qrow_f * ASA + qkof_f + ks * 16) * 2;
        ldsm_x4(qf[ks][0], qf[ks][1], qf[ks][2], qf[ks][3], qa);
    }

    float O[8][4];
#pragma unroll
    for (int jo = 0; jo < 8; jo++)
#pragma unroll
        for (int r = 0; r < 4; r++) O[jo][r] = 0.0f;
    float M0 = -3.0e38f, M1 = -3.0e38f, L0 = 0.0f, L1 = 0.0f;

    for (int kt = 0; kt < NKT; kt++) {
        if (kt + 1 < NKT) {
            load_kv(kt + 1, (kt + 1) & 1);
            CP_ASYNC_WAIT1();
        } else {
            CP_ASYNC_WAIT0();
        }
        __syncthreads();
        const uint32_t stage = sb + A_ST0 + (kt & 1) * A_STAGE;

        // ---- S = Qf @ (Kh + Kl)^T ----
        float s[16][4];
#pragma unroll
        for (int j = 0; j < 16; j++)
#pragma unroll
            for (int r = 0; r < 4; r++) s[j][r] = 0.0f;

#pragma unroll
        for (int ks = 0; ks < 4; ks++) {
#pragma unroll
            for (int jp = 0; jp < 8; jp++) {
                uint32_t kh[4], kl[4];
                uint32_t ka = stage + 0 * ATILE +
                    (uint32_t)((krow_f + jp * 16) * ASA + kkof_f + ks * 16) * 2;
                ldsm_x4(kh[0], kh[1], kh[2], kh[3], ka);
                ldsm_x4(kl[0], kl[1], kl[2], kl[3], ka + ATILE);
                mma_f16(s[jp * 2],     qf[ks], kh[0], kh[1]);
                mma_f16(s[jp * 2],     qf[ks], kl[0], kl[1]);
                mma_f16(s[jp * 2 + 1], qf[ks], kh[2], kh[3]);
                mma_f16(s[jp * 2 + 1], qf[ks], kl[2], kl[3]);
            }
        }

        // ---- online softmax (exp2 domain) ----
        float mx0 = -3.0e38f, mx1 = -3.0e38f;
#pragma unroll
        for (int j = 0; j < 16; j++) {
            mx0 = fmaxf(mx0, fmaxf(s[j][0], s[j][1]));
            mx1 = fmaxf(mx1, fmaxf(s[j][2], s[j][3]));
        }
        mx0 = fmaxf(mx0, __shfl_xor_sync(0xffffffffu, mx0, 1));
        mx0 = fmaxf(mx0, __shfl_xor_sync(0xffffffffu, mx0, 2));
        mx1 = fmaxf(mx1, __shfl_xor_sync(0xffffffffu, mx1, 1));
        mx1 = fmaxf(mx1, __shfl_xor_sync(0xffffffffu, mx1, 2));

        const float Mn0 = fmaxf(M0, mx0), Mn1 = fmaxf(M1, mx1);
        const float f0 = ex2(M0 - Mn0), f1 = ex2(M1 - Mn1);
        M0 = Mn0; M1 = Mn1;

        float sum0 = 0.0f, sum1 = 0.0f;
#pragma unroll
        for (int j = 0; j < 16; j++) {
            s[j][0] = ex2(s[j][0] - M0);
            s[j][1] = ex2(s[j][1] - M0);
            s[j][2] = ex2(s[j][2] - M1);
            s[j][3] = ex2(s[j][3] - M1);
            sum0 += s[j][0] + s[j][1];
            sum1 += s[j][2] + s[j][3];
        }
        sum0 += __shfl_xor_sync(0xffffffffu, sum0, 1);
        sum0 += __shfl_xor_sync(0xffffffffu, sum0, 2);
        sum1 += __shfl_xor_sync(0xffffffffu, sum1, 1);
        sum1 += __shfl_xor_sync(0xffffffffu, sum1, 2);
        L0 = L0 * f0 + sum0;
        L1 = L1 * f1 + sum1;

#pragma unroll
        for (int jo = 0; jo < 8; jo++) {
            O[jo][0] *= f0; O[jo][1] *= f0;
            O[jo][2] *= f1; O[jo][3] *= f1;
        }

        // ---- O += Pf @ (Vh + Vl) ----
#pragma unroll
        for (int ks2 = 0; ks2 < 8; ks2++) {
            uint32_t ph[4];
            ph[0] = packh(s[2 * ks2][0],     s[2 * ks2][1]);
            ph[1] = packh(s[2 * ks2][2],     s[2 * ks2][3]);
            ph[2] = packh(s[2 * ks2 + 1][0], s[2 * ks2 + 1][1]);
            ph[3] = packh(s[2 * ks2 + 1][2], s[2 * ks2 + 1][3]);
#pragma unroll
            for (int nn = 0; nn < 4; nn++) {
                uint32_t vh[4], vl[4];
                uint32_t va = stage + 2 * ATILE +
                    (uint32_t)((ks2 * 16 + vrow_f) * ASA + nn * 16 + vcol_f) * 2;
                ldsm_x4_t(vh[0], vh[1], vh[2], vh[3], va);
                ldsm_x4_t(vl[0], vl[1], vl[2], vl[3], va + ATILE);
                mma_f16(O[nn * 2],     ph, vh[0], vh[1]);
                mma_f16(O[nn * 2],     ph, vl[0], vl[1]);
                mma_f16(O[nn * 2 + 1], ph, vh[2], vh[3]);
                mma_f16(O[nn * 2 + 1], ph, vl[2], vl[3]);
            }
        }
        __syncthreads();
    }

    // ---- epilogue: normalize, fp16 hi/lo split for out projection ----
    const float il0 = 1.0f / L0, il1 = 1.0f / L1;
    const size_t r0 = qrow0 + qm + (lane >> 2);
    const size_t r1 = r0 + 8;
#pragma unroll
    for (int jo = 0; jo < 8; jo++) {
        const size_t col = hoff + jo * 8 + (lane & 3) * 2;
        uint32_t hp, lp;
        splitH2(O[jo][0] * il0, O[jo][1] * il0, hp, lp);
        *(uint32_t*)(Xh_ + r0 * DM + col) = hp;
        *(uint32_t*)(Xl_ + r0 * DM + col) = lp;
        splitH2(O[jo][2] * il1, O[jo][3] * il1, hp, lp);
        *(uint32_t*)(Xh_ + r1 * DM + col) = hp;
        *(uint32_t*)(Xl_ + r1 * DM + col) = lp;
    }
}

// ---------------------------------------------------------------------------
extern "C" void kernel_launch(void* const* d_in, const int* in_sizes, int n_in,
                              void* d_out, int out_size)
{
    const float* query = (const float*)d_in[0];
    const float* key   = (const float*)d_in[1];
    const float* value = (const float*)d_in[2];
    const float* Wq    = (const float*)d_in[3];
    const float* bq    = (const float*)d_in[4];
    const float* Wk    = (const float*)d_in[5];
    const float* bk    = (const float*)d_in[6];
    const float* Wv    = (const float*)d_in[7];
    const float* bv    = (const float*)d_in[8];
    const float* Wo    = (const float*)d_in[9];
    const float* bo    = (const float*)d_in[10];
    float* out = (float*)d_out;

    __half *qf, *kh, *kl, *vh, *vl, *xh, *xl;
    cudaGetSymbolAddress((void**)&qf, g_Qf);
    cudaGetSymbolAddress((void**)&kh, g_Kh);
    cudaGetSymbolAddress((void**)&kl, g_Kl);
    cudaGetSymbolAddress((void**)&vh, g_Vh);
    cudaGetSymbolAddress((void**)&vl, g_Vl);
    cudaGetSymbolAddress((void**)&xh, g_Xh);
    cudaGetSymbolAddress((void**)&xl, g_Xl);

    cudaFuncSetAttribute(qkv_gemm64,
                         cudaFuncAttributeMaxDynamicSharedMemorySize, GEMM_SMEM3);
    cudaFuncSetAttribute(out_gemm64,
                         cudaFuncAttributeMaxDynamicSharedMemorySize, GEMM_SMEM3);
    cudaFuncSetAttribute(attn_mma,
                         cudaFuncAttributeMaxDynamicSharedMemorySize, ATT_SMEM);

    split_inputs_kernel<<<dim3(2048, 1, 3), 256>>>(query, key, value);
    split_weights_kernel<<<dim3(512, 1, 4), 256>>>(Wq, Wk, Wv, Wo);

    qkv_gemm64<<<dim3(DM / 128, MROWS / 256, 3), 256, GEMM_SMEM3>>>(bq, bk, bv);

    attn_mma<<<dim3(SS / 128, HH, BB), 256, ATT_SMEM>>>(qf, kh, kl,
                                                        vh, vl, xh, xl);

    out_gemm64<<<dim3(DM / 128, MROWS / 256), 256, GEMM_SMEM3>>>(bo, out);
}

// round 11
// speedup vs baseline: 2.0193x; 1.5286x over previous
#include <cuda_runtime.h>
#include <cuda_bf16.h>
#include <cuda_fp16.h>
#include <cstdint>

// Problem constants
#define BB 4
#define SS 2048
#define DM 1024
#define HH 16
#define HD 64
#define MROWS (BB * SS)   // 8192

// Q pre-scale: (1/sqrt(D)) * log2(e) folded into Q projection output.
#define QSCALE 0.04508422002778011f

// Scratch (allocation-free rule: __device__ globals)
__device__ __half g_Aqf[MROWS * DM];                      // query, single fp16
__device__ __half g_Akf[MROWS * DM];                      // key
__device__ __half g_Avf[MROWS * DM];                      // value
__device__ __half g_Wqf[DM * DM], g_Wkf[DM * DM];         // weights single fp16
__device__ __half g_Wvf[DM * DM], g_Wof[DM * DM];
__device__ __half g_Qf[MROWS * DM];                       // Q proj (scaled)
__device__ __half g_Kh[MROWS * DM], g_Kl[MROWS * DM];     // K proj hi/lo
__device__ __half g_Vf[MROWS * DM];                       // V proj single
__device__ __half g_Xf[MROWS * DM];                       // attention out single

// ---------------------------------------------------------------------------
// Portable (sm_80+) tensor-core helpers
// ---------------------------------------------------------------------------
__device__ __forceinline__ uint32_t smem_to_u32(const void* p) {
    uint32_t a;
    asm("{ .reg .u64 t; cvta.to.shared.u64 t, %1; cvt.u32.u64 %0, t; }"
        : "=r"(a) : "l"(p));
    return a;
}

__device__ __forceinline__ void ldsm_x4(uint32_t& r0, uint32_t& r1,
                                        uint32_t& r2, uint32_t& r3,
                                        uint32_t addr) {
    asm volatile("ldmatrix.sync.aligned.m8n8.x4.shared.b16 {%0,%1,%2,%3}, [%4];"
                 : "=r"(r0), "=r"(r1), "=r"(r2), "=r"(r3) : "r"(addr));
}

__device__ __forceinline__ void ldsm_x4_t(uint32_t& r0, uint32_t& r1,
                                          uint32_t& r2, uint32_t& r3,
                                          uint32_t addr) {
    asm volatile("ldmatrix.sync.aligned.m8n8.x4.trans.shared.b16 {%0,%1,%2,%3}, [%4];"
                 : "=r"(r0), "=r"(r1), "=r"(r2), "=r"(r3) : "r"(addr));
}

__device__ __forceinline__ void mma_f16(float* c, const uint32_t* a,
                                        uint32_t b0, uint32_t b1) {
    asm volatile(
        "mma.sync.aligned.m16n8k16.row.col.f32.f16.f16.f32 "
        "{%0,%1,%2,%3}, {%4,%5,%6,%7}, {%8,%9}, {%0,%1,%2,%3};"
        : "+f"(c[0]), "+f"(c[1]), "+f"(c[2]), "+f"(c[3])
        : "r"(a[0]), "r"(a[1]), "r"(a[2]), "r"(a[3]), "r"(b0), "r"(b1));
}

__device__ __forceinline__ float ex2(float x) {
    float y;
    asm("ex2.approx.ftz.f32 %0, %1;" : "=f"(y) : "f"(x));
    return y;
}

#define CP_ASYNC_16(smem_u32, gptr) \
    asm volatile("cp.async.cg.shared.global [%0], [%1], 16;" \
        :: "r"(smem_u32), "l"(gptr) : "memory")
#define CP_ASYNC_COMMIT() asm volatile("cp.async.commit_group;" ::: "memory")
#define CP_ASYNC_WAIT1() asm volatile("cp.async.wait_group 1;" ::: "memory")
#define CP_ASYNC_WAIT0() asm volatile("cp.async.wait_group 0;" ::: "memory")

// fp16 pack (x -> low 16, y -> high 16)
__device__ __forceinline__ uint32_t packh(float x, float y) {
    __half2 h = __floats2half2_rn(x, y);
    return *(uint32_t*)&h;
}

// fp16 hi/lo split, two at a time
__device__ __forceinline__ void splitH2(float x, float y, uint32_t& hi, uint32_t& lo) {
    __half hx = __float2half_rn(x);
    __half hy = __float2half_rn(y);
    __half lx = __float2half_rn(x - __half2float(hx));
    __half ly = __float2half_rn(y - __half2float(hy));
    hi = ((uint32_t)__half_as_ushort(hy) << 16) | __half_as_ushort(hx);
    lo = ((uint32_t)__half_as_ushort(ly) << 16) | __half_as_ushort(lx);
}

// fp32 -> single fp16 convert
__device__ __forceinline__ void conv_body(const float* __restrict__ x,
                                          __half* __restrict__ f, int n4)
{
    int i = blockIdx.x * blockDim.x + threadIdx.x;
    int stride = gridDim.x * blockDim.x;
    for (; i < n4; i += stride) {
        float4 v = ((const float4*)x)[i];
        ((uint2*)f)[i] = make_uint2(packh(v.x, v.y), packh(v.z, v.w));
    }
}

__global__ __launch_bounds__(256) void conv_inputs_kernel(
    const float* __restrict__ q, const float* __restrict__ k,
    const float* __restrict__ v)
{
    const int n4 = MROWS * DM / 4;
    if (blockIdx.z == 0)      conv_body(q, g_Aqf, n4);
    else if (blockIdx.z == 1) conv_body(k, g_Akf, n4);
    else                      conv_body(v, g_Avf, n4);
}

__global__ __launch_bounds__(256) void conv_weights_kernel(
    const float* __restrict__ wq, const float* __restrict__ wk,
    const float* __restrict__ wv, const float* __restrict__ wo)
{
    const int n4 = DM * DM / 4;
    if (blockIdx.z == 0)      conv_body(wq, g_Wqf, n4);
    else if (blockIdx.z == 1) conv_body(wk, g_Wkf, n4);
    else if (blockIdx.z == 2) conv_body(wv, g_Wvf, n4);
    else                      conv_body(wo, g_Wof, n4);
}

// ---------------------------------------------------------------------------
// HMMA GEMM body, plain fp16 (1 MMA per product): C = Af @ Wf^T + bias.
// Block 256x128, BK=64, 8 warps x 64x64, 2-stage cp.async pipeline.
// OMODE: 0 = fp32 out; 1 = fp16 single (x oscale); 2 = fp16 hi/lo.
// ---------------------------------------------------------------------------
#define SA2    72
#define ATILE2 (256 * SA2 * 2)             // 36864 B (A 256x64 tile)
#define BTILE2 (128 * SA2 * 2)             // 18432 B (W 128x64 tile)
#define STG3   (ATILE2 + BTILE2)           // 55296 B
#define GEMM_SMEM3 (2 * STG3)              // 110592 B
#define BKC2   64
#define NCH2   (DM / BKC2)                 // 16
#define OFF_AF 0
#define OFF_WF ATILE2

template <int OMODE>
__device__ __forceinline__ void gemm64_body(
    const __half* __restrict__ Af, const __half* __restrict__ Wf,
    const float* __restrict__ bias, float oscale, float* __restrict__ C,
    void* __restrict__ O0, void* __restrict__ O1)
{
    extern __shared__ char smem[];
    const uint32_t sb = smem_to_u32(smem);
    const int tid  = threadIdx.x;
    const int wid  = tid >> 5;
    const int lane = tid & 31;
    const int bm = blockIdx.y * 256;
    const int bn = blockIdx.x * 128;
    const int wm = (wid >> 1) * 64;
    const int wn = (wid & 1) * 64;

    // A loader: thread t -> row t, full 128B row-chunk (8 x cp16)
    const char* gAf = (const char*)(Af + (size_t)(bm + tid) * DM);
    const uint32_t soA = (uint32_t)(tid * SA2 * 2);
    // W loader: thread t -> row t>>1, 64B half (4 x cp16)
    const int brow  = tid >> 1;
    const int bhalf = (tid & 1) * 64;
    const char* gWf = (const char*)(Wf + (size_t)(bn + brow) * DM) + bhalf;
    const uint32_t soB = (uint32_t)(brow * SA2 * 2) + bhalf;

    auto load_chunk = [&](int c, int stg) {
        const uint32_t base = sb + stg * STG3;
        const int gb = c * (BKC2 * 2);
#pragma unroll
        for (int s = 0; s < 8; s++)
            CP_ASYNC_16(base + OFF_AF + soA + s * 16, gAf + gb + s * 16);
#pragma unroll
        for (int s = 0; s < 4; s++)
            CP_ASYNC_16(base + OFF_WF + soB + s * 16, gWf + gb + s * 16);
        CP_ASYNC_COMMIT();
    };

    const int grp = lane >> 3, rin = lane & 7;
    const int a_row = wm + (grp & 1) * 8 + rin;
    const int a_kof = (grp >> 1) * 8;
    const int b_row = wn + (grp >> 1) * 8 + rin;
    const int b_kof = (grp & 1) * 8;

    float acc[4][8][4];
#pragma unroll
    for (int i = 0; i < 4; i++)
#pragma unroll
        for (int j = 0; j < 8; j++)
#pragma unroll
            for (int r = 0; r < 4; r++) acc[i][j][r] = 0.0f;

    load_chunk(0, 0);

    for (int c = 0; c < NCH2; c++) {
        CP_ASYNC_WAIT0();
        __syncthreads();
        if (c + 1 < NCH2) load_chunk(c + 1, (c + 1) & 1);

        const uint32_t base = sb + (c & 1) * STG3;
#pragma unroll
        for (int k0 = 0; k0 < BKC2; k0 += 16) {
            uint32_t af[4][4];
#pragma unroll
            for (int i = 0; i < 4; i++) {
                uint32_t ad = base + OFF_AF +
                    (uint32_t)((a_row + i * 16) * SA2 + k0 + a_kof) * 2;
                ldsm_x4(af[i][0], af[i][1], af[i][2], af[i][3], ad);
            }
            uint32_t wf[8][2];
#pragma unroll
            for (int jp = 0; jp < 4; jp++) {
                uint32_t bd = base + OFF_WF +
                    (uint32_t)((b_row + jp * 16) * SA2 + k0 + b_kof) * 2;
                ldsm_x4(wf[jp * 2][0], wf[jp * 2][1],
                        wf[jp * 2 + 1][0], wf[jp * 2 + 1][1], bd);
            }
#pragma unroll
            for (int i = 0; i < 4; i++)
#pragma unroll
                for (int j = 0; j < 8; j++)
                    mma_f16(acc[i][j], af[i], wf[j][0], wf[j][1]);
        }
    }

    const int erow = bm + wm + (lane >> 2);
    const int ecol = bn + wn + (lane & 3) * 2;
#pragma unroll
    for (int i = 0; i < 4; i++) {
#pragma unroll
        for (int j = 0; j < 8; j++) {
            const int col = ecol + j * 8;
            const float b0 = bias[col], b1 = bias[col + 1];
            const size_t o0 = (size_t)(erow + i * 16) * DM + col;
            const size_t o1 = (size_t)(erow + i * 16 + 8) * DM + col;
            const float c0 = (acc[i][j][0] + b0) * oscale;
            const float c1 = (acc[i][j][1] + b1) * oscale;
            const float c2 = (acc[i][j][2] + b0) * oscale;
            const float c3 = (acc[i][j][3] + b1) * oscale;
            if (OMODE == 0) {
                *(float2*)(C + o0) = make_float2(c0, c1);
                *(float2*)(C + o1) = make_float2(c2, c3);
            } else if (OMODE == 1) {
                __half* Of = (__half*)O0;
                *(uint32_t*)(Of + o0) = packh(c0, c1);
                *(uint32_t*)(Of + o1) = packh(c2, c3);
            } else {
                __half* Hh = (__half*)O0;
                __half* Hl = (__half*)O1;
                uint32_t hv, lv;
                splitH2(c0, c1, hv, lv);
                *(uint32_t*)(Hh + o0) = hv;
                *(uint32_t*)(Hl + o0) = lv;
                splitH2(c2, c3, hv, lv);
                *(uint32_t*)(Hh + o1) = hv;
                *(uint32_t*)(Hl + o1) = lv;
            }
        }
    }
}

__global__ __launch_bounds__(256, 1) void qkv_gemm64(
    const float* __restrict__ bq, const float* __restrict__ bk,
    const float* __restrict__ bv)
{
    if (blockIdx.z == 0)
        gemm64_body<1>(g_Aqf, g_Wqf, bq, QSCALE, nullptr, g_Qf, nullptr);
    else if (blockIdx.z == 1)
        gemm64_body<2>(g_Akf, g_Wkf, bk, 1.0f, nullptr, g_Kh, g_Kl);
    else
        gemm64_body<1>(g_Avf, g_Wvf, bv, 1.0f, nullptr, g_Vf, nullptr);
}

__global__ __launch_bounds__(256, 1) void out_gemm64(
    const float* __restrict__ bo, float* __restrict__ out)
{
    gemm64_body<0>(g_Xf, g_Wof, bo, 1.0f, out, nullptr, nullptr);
}

// ---------------------------------------------------------------------------
// HMMA flash attention. Q single fp16 (pre-scaled, exp2 domain),
// K fp16 hi/lo (2-MMA scores), V single fp16 (1-MMA PV).
// ---------------------------------------------------------------------------
#define ASA 72
#define ATILE (128 * ASA * 2)
#define A_QF 0
#define A_ST0 ATILE
#define A_STAGE (3 * ATILE)                 // Kh, Kl, Vf
#define ATT_SMEM (ATILE + 2 * A_STAGE)      // 129024 B
#define NKT (SS / 128)

__global__ __launch_bounds__(256, 1) void attn_mma(
    const __half* __restrict__ Qf_,
    const __half* __restrict__ Kh_, const __half* __restrict__ Kl_,
    const __half* __restrict__ Vf_,
    __half* __restrict__ Xf_)
{
    extern __shared__ char smem[];
    const uint32_t sb = smem_to_u32(smem);
    const int tid  = threadIdx.x;
    const int wid  = tid >> 5;
    const int lane = tid & 31;
    const int qm   = wid * 16;
    const int qb = blockIdx.x, h = blockIdx.y, b = blockIdx.z;
    const size_t qrow0 = (size_t)(b * SS + qb * 128);
    const size_t hoff  = (size_t)h * HD;

    // Q tile (single fp16) via cp.async (group 0)
#pragma unroll
    for (int i = 0; i < 4; i++) {
        int ci = tid + i * 256;
        int r = ci >> 3, cof = (ci & 7) * 16;
        uint32_t so = (uint32_t)(r * ASA * 2) + cof;
        CP_ASYNC_16(sb + A_QF + so,
                    (const char*)(Qf_ + (qrow0 + r) * DM + hoff) + cof);
    }
    CP_ASYNC_COMMIT();

    auto load_kv = [&](int kt, int stg) {
        const size_t k0 = (size_t)(b * SS + kt * 128);
        const uint32_t base = sb + A_ST0 + stg * A_STAGE;
#pragma unroll
        for (int i = 0; i < 4; i++) {
            int ci = tid + i * 256;
            int r = ci >> 3, cof = (ci & 7) * 16;
            uint32_t so = (uint32_t)(r * ASA * 2) + cof;
            const size_t g = (k0 + r) * DM + hoff;
            CP_ASYNC_16(base + 0 * ATILE + so, (const char*)(Kh_ + g) + cof);
            CP_ASYNC_16(base + 1 * ATILE + so, (const char*)(Kl_ + g) + cof);
            CP_ASYNC_16(base + 2 * ATILE + so, (const char*)(Vf_ + g) + cof);
        }
        CP_ASYNC_COMMIT();
    };

    load_kv(0, 0);    // group 1

    const int qrow_f = qm + (lane & 7) + ((lane >> 3) & 1) * 8;
    const int qkof_f = ((lane >> 4) & 1) * 8;
    const int krow_f = (lane & 7) + ((lane >> 4) & 1) * 8;
    const int kkof_f = ((lane >> 3) & 1) * 8;
    const int vrow_f = lane & 15;
    const int vcol_f = (lane >> 4) * 8;

    // Hoist Q fragments (Q group done after WAIT1)
    CP_ASYNC_WAIT1();
    __syncthreads();
    uint32_t qf[4][4];
#pragma unroll
    for (int ks = 0; ks < 4; ks++) {
        uint32_t qa = sb + A_QF + (uint32_t)(qrow_f * ASA + qkof_f + ks * 16) * 2;
        ldsm_x4(qf[ks][0], qf[ks][1], qf[ks][2], qf[ks][3], qa);
    }

    float O[8][4];
#pragma unroll
    for (int jo = 0; jo < 8; jo++)
#pragma unroll
        for (int r = 0; r < 4; r++) O[jo][r] = 0.0f;
    float M0 = -3.0e38f, M1 = -3.0e38f, L0 = 0.0f, L1 = 0.0f;

    for (int kt = 0; kt < NKT; kt++) {
        if (kt + 1 < NKT) {
            load_kv(kt + 1, (kt + 1) & 1);
            CP_ASYNC_WAIT1();
        } else {
            CP_ASYNC_WAIT0();
        }
        __syncthreads();
        const uint32_t stage = sb + A_ST0 + (kt & 1) * A_STAGE;

        // ---- S = Qf @ (Kh + Kl)^T ----
        float s[16][4];
#pragma unroll
        for (int j = 0; j < 16; j++)
#pragma unroll
            for (int r = 0; r < 4; r++) s[j][r] = 0.0f;

#pragma unroll
        for (int ks = 0; ks < 4; ks++) {
#pragma unroll
            for (int jp = 0; jp < 8; jp++) {
                uint32_t kh[4], kl[4];
                uint32_t ka = stage + 0 * ATILE +
                    (uint32_t)((krow_f + jp * 16) * ASA + kkof_f + ks * 16) * 2;
                ldsm_x4(kh[0], kh[1], kh[2], kh[3], ka);
                ldsm_x4(kl[0], kl[1], kl[2], kl[3], ka + ATILE);
                mma_f16(s[jp * 2],     qf[ks], kh[0], kh[1]);
                mma_f16(s[jp * 2],     qf[ks], kl[0], kl[1]);
                mma_f16(s[jp * 2 + 1], qf[ks], kh[2], kh[3]);
                mma_f16(s[jp * 2 + 1], qf[ks], kl[2], kl[3]);
            }
        }

        // ---- online softmax (exp2 domain) ----
        float mx0 = -3.0e38f, mx1 = -3.0e38f;
#pragma unroll
        for (int j = 0; j < 16; j++) {
            mx0 = fmaxf(mx0, fmaxf(s[j][0], s[j][1]));
            mx1 = fmaxf(mx1, fmaxf(s[j][2], s[j][3]));
        }
        mx0 = fmaxf(mx0, __shfl_xor_sync(0xffffffffu, mx0, 1));
        mx0 = fmaxf(mx0, __shfl_xor_sync(0xffffffffu, mx0, 2));
        mx1 = fmaxf(mx1, __shfl_xor_sync(0xffffffffu, mx1, 1));
        mx1 = fmaxf(mx1, __shfl_xor_sync(0xffffffffu, mx1, 2));

        const float Mn0 = fmaxf(M0, mx0), Mn1 = fmaxf(M1, mx1);
        const float f0 = ex2(M0 - Mn0), f1 = ex2(M1 - Mn1);
        M0 = Mn0; M1 = Mn1;

        float sum0 = 0.0f, sum1 = 0.0f;
#pragma unroll
        for (int j = 0; j < 16; j++) {
            s[j][0] = ex2(s[j][0] - M0);
            s[j][1] = ex2(s[j][1] - M0);
            s[j][2] = ex2(s[j][2] - M1);
            s[j][3] = ex2(s[j][3] - M1);
            sum0 += s[j][0] + s[j][1];
            sum1 += s[j][2] + s[j][3];
        }
        sum0 += __shfl_xor_sync(0xffffffffu, sum0, 1);
        sum0 += __shfl_xor_sync(0xffffffffu, sum0, 2);
        sum1 += __shfl_xor_sync(0xffffffffu, sum1, 1);
        sum1 += __shfl_xor_sync(0xffffffffu, sum1, 2);
        L0 = L0 * f0 + sum0;
        L1 = L1 * f1 + sum1;

#pragma unroll
        for (int jo = 0; jo < 8; jo++) {
            O[jo][0] *= f0; O[jo][1] *= f0;
            O[jo][2] *= f1; O[jo][3] *= f1;
        }

        // ---- O += Pf @ Vf  (1 MMA per n8-pair) ----
#pragma unroll
        for (int ks2 = 0; ks2 < 8; ks2++) {
            uint32_t ph[4];
            ph[0] = packh(s[2 * ks2][0],     s[2 * ks2][1]);
            ph[1] = packh(s[2 * ks2][2],     s[2 * ks2][3]);
            ph[2] = packh(s[2 * ks2 + 1][0], s[2 * ks2 + 1][1]);
            ph[3] = packh(s[2 * ks2 + 1][2], s[2 * ks2 + 1][3]);
#pragma unroll
            for (int nn = 0; nn < 4; nn++) {
                uint32_t vf[4];
                uint32_t va = stage + 2 * ATILE +
                    (uint32_t)((ks2 * 16 + vrow_f) * ASA + nn * 16 + vcol_f) * 2;
                ldsm_x4_t(vf[0], vf[1], vf[2], vf[3], va);
                mma_f16(O[nn * 2],     ph, vf[0], vf[1]);
                mma_f16(O[nn * 2 + 1], ph, vf[2], vf[3]);
            }
        }
        __syncthreads();
    }

    // ---- epilogue: normalize, single fp16 out ----
    const float il0 = 1.0f / L0, il1 = 1.0f / L1;
    const size_t r0 = qrow0 + qm + (lane >> 2);
    const size_t r1 = r0 + 8;
#pragma unroll
    for (int jo = 0; jo < 8; jo++) {
        const size_t col = hoff + jo * 8 + (lane & 3) * 2;
        *(uint32_t*)(Xf_ + r0 * DM + col) = packh(O[jo][0] * il0, O[jo][1] * il0);
        *(uint32_t*)(Xf_ + r1 * DM + col) = packh(O[jo][2] * il1, O[jo][3] * il1);
    }
}

// ---------------------------------------------------------------------------
extern "C" void kernel_launch(void* const* d_in, const int* in_sizes, int n_in,
                              void* d_out, int out_size)
{
    const float* query = (const float*)d_in[0];
    const float* key   = (const float*)d_in[1];
    const float* value = (const float*)d_in[2];
    const float* Wq    = (const float*)d_in[3];
    const float* bq    = (const float*)d_in[4];
    const float* Wk    = (const float*)d_in[5];
    const float* bk    = (const float*)d_in[6];
    const float* Wv    = (const float*)d_in[7];
    const float* bv    = (const float*)d_in[8];
    const float* Wo    = (const float*)d_in[9];
    const float* bo    = (const float*)d_in[10];
    float* out = (float*)d_out;

    __half *qf, *kh, *kl, *vf, *xf;
    cudaGetSymbolAddress((void**)&qf, g_Qf);
    cudaGetSymbolAddress((void**)&kh, g_Kh);
    cudaGetSymbolAddress((void**)&kl, g_Kl);
    cudaGetSymbolAddress((void**)&vf, g_Vf);
    cudaGetSymbolAddress((void**)&xf, g_Xf);

    cudaFuncSetAttribute(qkv_gemm64,
                         cudaFuncAttributeMaxDynamicSharedMemorySize, GEMM_SMEM3);
    cudaFuncSetAttribute(out_gemm64,
                         cudaFuncAttributeMaxDynamicSharedMemorySize, GEMM_SMEM3);
    cudaFuncSetAttribute(attn_mma,
                         cudaFuncAttributeMaxDynamicSharedMemorySize, ATT_SMEM);

    conv_inputs_kernel<<<dim3(2048, 1, 3), 256>>>(query, key, value);
    conv_weights_kernel<<<dim3(512, 1, 4), 256>>>(Wq, Wk, Wv, Wo);

    qkv_gemm64<<<dim3(DM / 128, MROWS / 256, 3), 256, GEMM_SMEM3>>>(bq, bk, bv);

    attn_mma<<<dim3(SS / 128, HH, BB), 256, ATT_SMEM>>>(qf, kh, kl, vf, xf);

    out_gemm64<<<dim3(DM / 128, MROWS / 256), 256, GEMM_SMEM3>>>(bo, out);
}

// round 12
// speedup vs baseline: 2.2859x; 1.1320x over previous
#include <cuda_runtime.h>
#include <cuda_bf16.h>
#include <cuda_fp16.h>
#include <cstdint>

// Problem constants
#define BB 4
#define SS 2048
#define DM 1024
#define HH 16
#define HD 64
#define MROWS (BB * SS)   // 8192

// Q pre-scale: (1/sqrt(D)) * log2(e) folded into Q projection output.
#define QSCALE 0.04508422002778011f

// Scratch (allocation-free rule: __device__ globals)
__device__ __half g_Aqf[MROWS * DM];                      // query, single fp16
__device__ __half g_Akf[MROWS * DM];                      // key
__device__ __half g_Avf[MROWS * DM];                      // value
__device__ __half g_Wqf[DM * DM], g_Wkf[DM * DM];         // weights single fp16
__device__ __half g_Wvf[DM * DM], g_Wof[DM * DM];
__device__ __half g_Qf[MROWS * DM];                       // Q proj (scaled)
__device__ __half g_Kf[MROWS * DM];                       // K proj single
__device__ __half g_Vf[MROWS * DM];                       // V proj single
__device__ __half g_Xf[MROWS * DM];                       // attention out single

// ---------------------------------------------------------------------------
// Portable (sm_80+) tensor-core helpers
// ---------------------------------------------------------------------------
__device__ __forceinline__ uint32_t smem_to_u32(const void* p) {
    uint32_t a;
    asm("{ .reg .u64 t; cvta.to.shared.u64 t, %1; cvt.u32.u64 %0, t; }"
        : "=r"(a) : "l"(p));
    return a;
}

__device__ __forceinline__ void ldsm_x4(uint32_t& r0, uint32_t& r1,
                                        uint32_t& r2, uint32_t& r3,
                                        uint32_t addr) {
    asm volatile("ldmatrix.sync.aligned.m8n8.x4.shared.b16 {%0,%1,%2,%3}, [%4];"
                 : "=r"(r0), "=r"(r1), "=r"(r2), "=r"(r3) : "r"(addr));
}

__device__ __forceinline__ void ldsm_x4_t(uint32_t& r0, uint32_t& r1,
                                          uint32_t& r2, uint32_t& r3,
                                          uint32_t addr) {
    asm volatile("ldmatrix.sync.aligned.m8n8.x4.trans.shared.b16 {%0,%1,%2,%3}, [%4];"
                 : "=r"(r0), "=r"(r1), "=r"(r2), "=r"(r3) : "r"(addr));
}

__device__ __forceinline__ void mma_f16(float* c, const uint32_t* a,
                                        uint32_t b0, uint32_t b1) {
    asm volatile(
        "mma.sync.aligned.m16n8k16.row.col.f32.f16.f16.f32 "
        "{%0,%1,%2,%3}, {%4,%5,%6,%7}, {%8,%9}, {%0,%1,%2,%3};"
        : "+f"(c[0]), "+f"(c[1]), "+f"(c[2]), "+f"(c[3])
        : "r"(a[0]), "r"(a[1]), "r"(a[2]), "r"(a[3]), "r"(b0), "r"(b1));
}

__device__ __forceinline__ float ex2(float x) {
    float y;
    asm("ex2.approx.ftz.f32 %0, %1;" : "=f"(y) : "f"(x));
    return y;
}

#define CP_ASYNC_16(smem_u32, gptr) \
    asm volatile("cp.async.cg.shared.global [%0], [%1], 16;" \
        :: "r"(smem_u32), "l"(gptr) : "memory")
#define CP_ASYNC_COMMIT() asm volatile("cp.async.commit_group;" ::: "memory")
#define CP_ASYNC_WAIT1() asm volatile("cp.async.wait_group 1;" ::: "memory")
#define CP_ASYNC_WAIT0() asm volatile("cp.async.wait_group 0;" ::: "memory")

// fp16 pack (x -> low 16, y -> high 16)
__device__ __forceinline__ uint32_t packh(float x, float y) {
    __half2 h = __floats2half2_rn(x, y);
    return *(uint32_t*)&h;
}

// fp32 -> single fp16 convert
__device__ __forceinline__ void conv_body(const float* __restrict__ x,
                                          __half* __restrict__ f, int n4)
{
    int i = blockIdx.x * blockDim.x + threadIdx.x;
    int stride = gridDim.x * blockDim.x;
    for (; i < n4; i += stride) {
        float4 v = ((const float4*)x)[i];
        ((uint2*)f)[i] = make_uint2(packh(v.x, v.y), packh(v.z, v.w));
    }
}

__global__ __launch_bounds__(256) void conv_inputs_kernel(
    const float* __restrict__ q, const float* __restrict__ k,
    const float* __restrict__ v)
{
    const int n4 = MROWS * DM / 4;
    if (blockIdx.z == 0)      conv_body(q, g_Aqf, n4);
    else if (blockIdx.z == 1) conv_body(k, g_Akf, n4);
    else                      conv_body(v, g_Avf, n4);
}

__global__ __launch_bounds__(256) void conv_weights_kernel(
    const float* __restrict__ wq, const float* __restrict__ wk,
    const float* __restrict__ wv, const float* __restrict__ wo)
{
    const int n4 = DM * DM / 4;
    if (blockIdx.z == 0)      conv_body(wq, g_Wqf, n4);
    else if (blockIdx.z == 1) conv_body(wk, g_Wkf, n4);
    else if (blockIdx.z == 2) conv_body(wv, g_Wvf, n4);
    else                      conv_body(wo, g_Wof, n4);
}

// ---------------------------------------------------------------------------
// HMMA GEMM body, plain fp16 (1 MMA per product): C = Af @ Wf^T + bias.
// Block 256x128, BK=64, 8 warps x 64x64, 2-stage cp.async pipeline.
// OMODE: 0 = fp32 out; 1 = fp16 single (x oscale).
// ---------------------------------------------------------------------------
#define SA2    72
#define ATILE2 (256 * SA2 * 2)             // 36864 B (A 256x64 tile)
#define BTILE2 (128 * SA2 * 2)             // 18432 B (W 128x64 tile)
#define STG3   (ATILE2 + BTILE2)           // 55296 B
#define GEMM_SMEM3 (2 * STG3)              // 110592 B
#define BKC2   64
#define NCH2   (DM / BKC2)                 // 16
#define OFF_AF 0
#define OFF_WF ATILE2

template <int OMODE>
__device__ __forceinline__ void gemm64_body(
    const __half* __restrict__ Af, const __half* __restrict__ Wf,
    const float* __restrict__ bias, float oscale, float* __restrict__ C,
    __half* __restrict__ Of)
{
    extern __shared__ char smem[];
    const uint32_t sb = smem_to_u32(smem);
    const int tid  = threadIdx.x;
    const int wid  = tid >> 5;
    const int lane = tid & 31;
    const int bm = blockIdx.y * 256;
    const int bn = blockIdx.x * 128;
    const int wm = (wid >> 1) * 64;
    const int wn = (wid & 1) * 64;

    const char* gAf = (const char*)(Af + (size_t)(bm + tid) * DM);
    const uint32_t soA = (uint32_t)(tid * SA2 * 2);
    const int brow  = tid >> 1;
    const int bhalf = (tid & 1) * 64;
    const char* gWf = (const char*)(Wf + (size_t)(bn + brow) * DM) + bhalf;
    const uint32_t soB = (uint32_t)(brow * SA2 * 2) + bhalf;

    auto load_chunk = [&](int c, int stg) {
        const uint32_t base = sb + stg * STG3;
        const int gb = c * (BKC2 * 2);
#pragma unroll
        for (int s = 0; s < 8; s++)
            CP_ASYNC_16(base + OFF_AF + soA + s * 16, gAf + gb + s * 16);
#pragma unroll
        for (int s = 0; s < 4; s++)
            CP_ASYNC_16(base + OFF_WF + soB + s * 16, gWf + gb + s * 16);
        CP_ASYNC_COMMIT();
    };

    const int grp = lane >> 3, rin = lane & 7;
    const int a_row = wm + (grp & 1) * 8 + rin;
    const int a_kof = (grp >> 1) * 8;
    const int b_row = wn + (grp >> 1) * 8 + rin;
    const int b_kof = (grp & 1) * 8;

    float acc[4][8][4];
#pragma unroll
    for (int i = 0; i < 4; i++)
#pragma unroll
        for (int j = 0; j < 8; j++)
#pragma unroll
            for (int r = 0; r < 4; r++) acc[i][j][r] = 0.0f;

    load_chunk(0, 0);

    for (int c = 0; c < NCH2; c++) {
        CP_ASYNC_WAIT0();
        __syncthreads();
        if (c + 1 < NCH2) load_chunk(c + 1, (c + 1) & 1);

        const uint32_t base = sb + (c & 1) * STG3;
#pragma unroll
        for (int k0 = 0; k0 < BKC2; k0 += 16) {
            uint32_t af[4][4];
#pragma unroll
            for (int i = 0; i < 4; i++) {
                uint32_t ad = base + OFF_AF +
                    (uint32_t)((a_row + i * 16) * SA2 + k0 + a_kof) * 2;
                ldsm_x4(af[i][0], af[i][1], af[i][2], af[i][3], ad);
            }
            uint32_t wf[8][2];
#pragma unroll
            for (int jp = 0; jp < 4; jp++) {
                uint32_t bd = base + OFF_WF +
                    (uint32_t)((b_row + jp * 16) * SA2 + k0 + b_kof) * 2;
                ldsm_x4(wf[jp * 2][0], wf[jp * 2][1],
                        wf[jp * 2 + 1][0], wf[jp * 2 + 1][1], bd);
            }
#pragma unroll
            for (int i = 0; i < 4; i++)
#pragma unroll
                for (int j = 0; j < 8; j++)
                    mma_f16(acc[i][j], af[i], wf[j][0], wf[j][1]);
        }
    }

    const int erow = bm + wm + (lane >> 2);
    const int ecol = bn + wn + (lane & 3) * 2;
#pragma unroll
    for (int i = 0; i < 4; i++) {
#pragma unroll
        for (int j = 0; j < 8; j++) {
            const int col = ecol + j * 8;
            const float b0 = bias[col], b1 = bias[col + 1];
            const size_t o0 = (size_t)(erow + i * 16) * DM + col;
            const size_t o1 = (size_t)(erow + i * 16 + 8) * DM + col;
            const float c0 = (acc[i][j][0] + b0) * oscale;
            const float c1 = (acc[i][j][1] + b1) * oscale;
            const float c2 = (acc[i][j][2] + b0) * oscale;
            const float c3 = (acc[i][j][3] + b1) * oscale;
            if (OMODE == 0) {
                *(float2*)(C + o0) = make_float2(c0, c1);
                *(float2*)(C + o1) = make_float2(c2, c3);
            } else {
                *(uint32_t*)(Of + o0) = packh(c0, c1);
                *(uint32_t*)(Of + o1) = packh(c2, c3);
            }
        }
    }
}

__global__ __launch_bounds__(256, 1) void qkv_gemm64(
    const float* __restrict__ bq, const float* __restrict__ bk,
    const float* __restrict__ bv)
{
    if (blockIdx.z == 0)
        gemm64_body<1>(g_Aqf, g_Wqf, bq, QSCALE, nullptr, g_Qf);
    else if (blockIdx.z == 1)
        gemm64_body<1>(g_Akf, g_Wkf, bk, 1.0f, nullptr, g_Kf);
    else
        gemm64_body<1>(g_Avf, g_Wvf, bv, 1.0f, nullptr, g_Vf);
}

__global__ __launch_bounds__(256, 1) void out_gemm64(
    const float* __restrict__ bo, float* __restrict__ out)
{
    gemm64_body<0>(g_Xf, g_Wof, bo, 1.0f, out, nullptr);
}

// ---------------------------------------------------------------------------
// HMMA flash attention, all-1-MMA fp16.
// Q single fp16 (pre-scaled, exp2 domain), K single fp16, V single fp16.
// ---------------------------------------------------------------------------
#define ASA 72
#define ATILE (128 * ASA * 2)
#define A_QF 0
#define A_ST0 ATILE
#define A_STAGE (2 * ATILE)                 // Kf, Vf
#define ATT_SMEM (ATILE + 2 * A_STAGE)      // 92160 B
#define NKT (SS / 128)

__global__ __launch_bounds__(256, 1) void attn_mma(
    const __half* __restrict__ Qf_, const __half* __restrict__ Kf_,
    const __half* __restrict__ Vf_, __half* __restrict__ Xf_)
{
    extern __shared__ char smem[];
    const uint32_t sb = smem_to_u32(smem);
    const int tid  = threadIdx.x;
    const int wid  = tid >> 5;
    const int lane = tid & 31;
    const int qm   = wid * 16;
    const int qb = blockIdx.x, h = blockIdx.y, b = blockIdx.z;
    const size_t qrow0 = (size_t)(b * SS + qb * 128);
    const size_t hoff  = (size_t)h * HD;

    // Q tile (single fp16) via cp.async (group 0)
#pragma unroll
    for (int i = 0; i < 4; i++) {
        int ci = tid + i * 256;
        int r = ci >> 3, cof = (ci & 7) * 16;
        uint32_t so = (uint32_t)(r * ASA * 2) + cof;
        CP_ASYNC_16(sb + A_QF + so,
                    (const char*)(Qf_ + (qrow0 + r) * DM + hoff) + cof);
    }
    CP_ASYNC_COMMIT();

    auto load_kv = [&](int kt, int stg) {
        const size_t k0 = (size_t)(b * SS + kt * 128);
        const uint32_t base = sb + A_ST0 + stg * A_STAGE;
#pragma unroll
        for (int i = 0; i < 4; i++) {
            int ci = tid + i * 256;
            int r = ci >> 3, cof = (ci & 7) * 16;
            uint32_t so = (uint32_t)(r * ASA * 2) + cof;
            const size_t g = (k0 + r) * DM + hoff;
            CP_ASYNC_16(base + 0 * ATILE + so, (const char*)(Kf_ + g) + cof);
            CP_ASYNC_16(base + 1 * ATILE + so, (const char*)(Vf_ + g) + cof);
        }
        CP_ASYNC_COMMIT();
    };

    load_kv(0, 0);    // group 1

    const int qrow_f = qm + (lane & 7) + ((lane >> 3) & 1) * 8;
    const int qkof_f = ((lane >> 4) & 1) * 8;
    const int krow_f = (lane & 7) + ((lane >> 4) & 1) * 8;
    const int kkof_f = ((lane >> 3) & 1) * 8;
    const int vrow_f = lane & 15;
    const int vcol_f = (lane >> 4) * 8;

    // Hoist Q fragments (Q group done after WAIT1)
    CP_ASYNC_WAIT1();
    __syncthreads();
    uint32_t qf[4][4];
#pragma unroll
    for (int ks = 0; ks < 4; ks++) {
        uint32_t qa = sb + A_QF + (uint32_t)(qrow_f * ASA + qkof_f + ks * 16) * 2;
        ldsm_x4(qf[ks][0], qf[ks][1], qf[ks][2], qf[ks][3], qa);
    }

    float O[8][4];
#pragma unroll
    for (int jo = 0; jo < 8; jo++)
#pragma unroll
        for (int r = 0; r < 4; r++) O[jo][r] = 0.0f;
    float M0 = -3.0e38f, M1 = -3.0e38f, L0 = 0.0f, L1 = 0.0f;

    for (int kt = 0; kt < NKT; kt++) {
        if (kt + 1 < NKT) {
            load_kv(kt + 1, (kt + 1) & 1);
            CP_ASYNC_WAIT1();
        } else {
            CP_ASYNC_WAIT0();
        }
        __syncthreads();
        const uint32_t stage = sb + A_ST0 + (kt & 1) * A_STAGE;

        // ---- S = Qf @ Kf^T  (1 MMA per n8-tile) ----
        float s[16][4];
#pragma unroll
        for (int j = 0; j < 16; j++)
#pragma unroll
            for (int r = 0; r < 4; r++) s[j][r] = 0.0f;

#pragma unroll
        for (int ks = 0; ks < 4; ks++) {
#pragma unroll
            for (int jp = 0; jp < 8; jp++) {
                uint32_t kf[4];
                uint32_t ka = stage + 0 * ATILE +
                    (uint32_t)((krow_f + jp * 16) * ASA + kkof_f + ks * 16) * 2;
                ldsm_x4(kf[0], kf[1], kf[2], kf[3], ka);
                mma_f16(s[jp * 2],     qf[ks], kf[0], kf[1]);
                mma_f16(s[jp * 2 + 1], qf[ks], kf[2], kf[3]);
            }
        }

        // ---- online softmax (exp2 domain) ----
        float mx0 = -3.0e38f, mx1 = -3.0e38f;
#pragma unroll
        for (int j = 0; j < 16; j++) {
            mx0 = fmaxf(mx0, fmaxf(s[j][0], s[j][1]));
            mx1 = fmaxf(mx1, fmaxf(s[j][2], s[j][3]));
        }
        mx0 = fmaxf(mx0, __shfl_xor_sync(0xffffffffu, mx0, 1));
        mx0 = fmaxf(mx0, __shfl_xor_sync(0xffffffffu, mx0, 2));
        mx1 = fmaxf(mx1, __shfl_xor_sync(0xffffffffu, mx1, 1));
        mx1 = fmaxf(mx1, __shfl_xor_sync(0xffffffffu, mx1, 2));

        const float Mn0 = fmaxf(M0, mx0), Mn1 = fmaxf(M1, mx1);
        const float f0 = ex2(M0 - Mn0), f1 = ex2(M1 - Mn1);
        M0 = Mn0; M1 = Mn1;

        float sum0 = 0.0f, sum1 = 0.0f;
#pragma unroll
        for (int j = 0; j < 16; j++) {
            s[j][0] = ex2(s[j][0] - M0);
            s[j][1] = ex2(s[j][1] - M0);
            s[j][2] = ex2(s[j][2] - M1);
            s[j][3] = ex2(s[j][3] - M1);
            sum0 += s[j][0] + s[j][1];
            sum1 += s[j][2] + s[j][3];
        }
        sum0 += __shfl_xor_sync(0xffffffffu, sum0, 1);
        sum0 += __shfl_xor_sync(0xffffffffu, sum0, 2);
        sum1 += __shfl_xor_sync(0xffffffffu, sum1, 1);
        sum1 += __shfl_xor_sync(0xffffffffu, sum1, 2);
        L0 = L0 * f0 + sum0;
        L1 = L1 * f1 + sum1;

#pragma unroll
        for (int jo = 0; jo < 8; jo++) {
            O[jo][0] *= f0; O[jo][1] *= f0;
            O[jo][2] *= f1; O[jo][3] *= f1;
        }

        // ---- O += Pf @ Vf  (1 MMA per n8-pair) ----
#pragma unroll
        for (int ks2 = 0; ks2 < 8; ks2++) {
            uint32_t ph[4];
            ph[0] = packh(s[2 * ks2][0],     s[2 * ks2][1]);
            ph[1] = packh(s[2 * ks2][2],     s[2 * ks2][3]);
            ph[2] = packh(s[2 * ks2 + 1][0], s[2 * ks2 + 1][1]);
            ph[3] = packh(s[2 * ks2 + 1][2], s[2 * ks2 + 1][3]);
#pragma unroll
            for (int nn = 0; nn < 4; nn++) {
                uint32_t vf[4];
                uint32_t va = stage + 1 * ATILE +
                    (uint32_t)((ks2 * 16 + vrow_f) * ASA + nn * 16 + vcol_f) * 2;
                ldsm_x4_t(vf[0], vf[1], vf[2], vf[3], va);
                mma_f16(O[nn * 2],     ph, vf[0], vf[1]);
                mma_f16(O[nn * 2 + 1], ph, vf[2], vf[3]);
            }
        }
        __syncthreads();
    }

    // ---- epilogue: normalize, single fp16 out ----
    const float il0 = 1.0f / L0, il1 = 1.0f / L1;
    const size_t r0 = qrow0 + qm + (lane >> 2);
    const size_t r1 = r0 + 8;
#pragma unroll
    for (int jo = 0; jo < 8; jo++) {
        const size_t col = hoff + jo * 8 + (lane & 3) * 2;
        *(uint32_t*)(Xf_ + r0 * DM + col) = packh(O[jo][0] * il0, O[jo][1] * il0);
        *(uint32_t*)(Xf_ + r1 * DM + col) = packh(O[jo][2] * il1, O[jo][3] * il1);
    }
}

// ---------------------------------------------------------------------------
extern "C" void kernel_launch(void* const* d_in, const int* in_sizes, int n_in,
                              void* d_out, int out_size)
{
    const float* query = (const float*)d_in[0];
    const float* key   = (const float*)d_in[1];
    const float* value = (const float*)d_in[2];
    const float* Wq    = (const float*)d_in[3];
    const float* bq    = (const float*)d_in[4];
    const float* Wk    = (const float*)d_in[5];
    const float* bk    = (const float*)d_in[6];
    const float* Wv    = (const float*)d_in[7];
    const float* bv    = (const float*)d_in[8];
    const float* Wo    = (const float*)d_in[9];
    const float* bo    = (const float*)d_in[10];
    float* out = (float*)d_out;

    __half *qf, *kf, *vf, *xf;
    cudaGetSymbolAddress((void**)&qf, g_Qf);
    cudaGetSymbolAddress((void**)&kf, g_Kf);
    cudaGetSymbolAddress((void**)&vf, g_Vf);
    cudaGetSymbolAddress((void**)&xf, g_Xf);

    cudaFuncSetAttribute(qkv_gemm64,
                         cudaFuncAttributeMaxDynamicSharedMemorySize, GEMM_SMEM3);
    cudaFuncSetAttribute(out_gemm64,
                         cudaFuncAttributeMaxDynamicSharedMemorySize, GEMM_SMEM3);
    cudaFuncSetAttribute(attn_mma,
                         cudaFuncAttributeMaxDynamicSharedMemorySize, ATT_SMEM);

    conv_inputs_kernel<<<dim3(2048, 1, 3), 256>>>(query, key, value);
    conv_weights_kernel<<<dim3(512, 1, 4), 256>>>(Wq, Wk, Wv, Wo);

    qkv_gemm64<<<dim3(DM / 128, MROWS / 256, 3), 256, GEMM_SMEM3>>>(bq, bk, bv);

    attn_mma<<<dim3(SS / 128, HH, BB), 256, ATT_SMEM>>>(qf, kf, vf, xf);

    out_gemm64<<<dim3(DM / 128, MROWS / 256), 256, GEMM_SMEM3>>>(bo, out);
}

// round 13
// speedup vs baseline: 2.5055x; 1.0961x over previous
#include <cuda_runtime.h>
#include <cuda_bf16.h>
#include <cuda_fp16.h>
#include <cstdint>

// Problem constants
#define BB 4
#define SS 2048
#define DM 1024
#define HH 16
#define HD 64
#define MROWS (BB * SS)   // 8192

// Q pre-scale: (1/sqrt(D)) * log2(e) folded into Q projection output.
#define QSCALE 0.04508422002778011f

// Scratch (allocation-free rule: __device__ globals)
__device__ __half g_Aqf[MROWS * DM];                      // query, single fp16
__device__ __half g_Akf[MROWS * DM];                      // key
__device__ __half g_Avf[MROWS * DM];                      // value
__device__ __half g_Wqf[DM * DM], g_Wkf[DM * DM];         // weights single fp16
__device__ __half g_Wvf[DM * DM], g_Wof[DM * DM];
__device__ __half g_Qf[MROWS * DM];                       // Q proj (scaled)
__device__ __half g_Kf[MROWS * DM];                       // K proj single
__device__ __half g_Vf[MROWS * DM];                       // V proj single
__device__ __half g_Xf[MROWS * DM];                       // attention out single

// ---------------------------------------------------------------------------
// Portable (sm_80+) tensor-core helpers
// ---------------------------------------------------------------------------
__device__ __forceinline__ uint32_t smem_to_u32(const void* p) {
    uint32_t a;
    asm("{ .reg .u64 t; cvta.to.shared.u64 t, %1; cvt.u32.u64 %0, t; }"
        : "=r"(a) : "l"(p));
    return a;
}

__device__ __forceinline__ void ldsm_x4(uint32_t& r0, uint32_t& r1,
                                        uint32_t& r2, uint32_t& r3,
                                        uint32_t addr) {
    asm volatile("ldmatrix.sync.aligned.m8n8.x4.shared.b16 {%0,%1,%2,%3}, [%4];"
                 : "=r"(r0), "=r"(r1), "=r"(r2), "=r"(r3) : "r"(addr));
}

__device__ __forceinline__ void ldsm_x4_t(uint32_t& r0, uint32_t& r1,
                                          uint32_t& r2, uint32_t& r3,
                                          uint32_t addr) {
    asm volatile("ldmatrix.sync.aligned.m8n8.x4.trans.shared.b16 {%0,%1,%2,%3}, [%4];"
                 : "=r"(r0), "=r"(r1), "=r"(r2), "=r"(r3) : "r"(addr));
}

__device__ __forceinline__ void mma_f16(float* c, const uint32_t* a,
                                        uint32_t b0, uint32_t b1) {
    asm volatile(
        "mma.sync.aligned.m16n8k16.row.col.f32.f16.f16.f32 "
        "{%0,%1,%2,%3}, {%4,%5,%6,%7}, {%8,%9}, {%0,%1,%2,%3};"
        : "+f"(c[0]), "+f"(c[1]), "+f"(c[2]), "+f"(c[3])
        : "r"(a[0]), "r"(a[1]), "r"(a[2]), "r"(a[3]), "r"(b0), "r"(b1));
}

__device__ __forceinline__ float ex2(float x) {
    float y;
    asm("ex2.approx.ftz.f32 %0, %1;" : "=f"(y) : "f"(x));
    return y;
}

#define CP_ASYNC_16(smem_u32, gptr) \
    asm volatile("cp.async.cg.shared.global [%0], [%1], 16;" \
        :: "r"(smem_u32), "l"(gptr) : "memory")
#define CP_ASYNC_COMMIT() asm volatile("cp.async.commit_group;" ::: "memory")
#define CP_ASYNC_WAIT1() asm volatile("cp.async.wait_group 1;" ::: "memory")
#define CP_ASYNC_WAIT0() asm volatile("cp.async.wait_group 0;" ::: "memory")

// fp16 pack (x -> low 16, y -> high 16)
__device__ __forceinline__ uint32_t packh(float x, float y) {
    __half2 h = __floats2half2_rn(x, y);
    return *(uint32_t*)&h;
}

// fp32 -> single fp16 convert
__device__ __forceinline__ void conv_body(const float* __restrict__ x,
                                          __half* __restrict__ f, int n4)
{
    int i = blockIdx.x * blockDim.x + threadIdx.x;
    int stride = gridDim.x * blockDim.x;
    for (; i < n4; i += stride) {
        float4 v = ((const float4*)x)[i];
        ((uint2*)f)[i] = make_uint2(packh(v.x, v.y), packh(v.z, v.w));
    }
}

__global__ __launch_bounds__(256) void conv_inputs_kernel(
    const float* __restrict__ q, const float* __restrict__ k,
    const float* __restrict__ v)
{
    const int n4 = MROWS * DM / 4;
    if (blockIdx.z == 0)      conv_body(q, g_Aqf, n4);
    else if (blockIdx.z == 1) conv_body(k, g_Akf, n4);
    else                      conv_body(v, g_Avf, n4);
}

__global__ __launch_bounds__(256) void conv_weights_kernel(
    const float* __restrict__ wq, const float* __restrict__ wk,
    const float* __restrict__ wv, const float* __restrict__ wo)
{
    const int n4 = DM * DM / 4;
    if (blockIdx.z == 0)      conv_body(wq, g_Wqf, n4);
    else if (blockIdx.z == 1) conv_body(wk, g_Wkf, n4);
    else if (blockIdx.z == 2) conv_body(wv, g_Wvf, n4);
    else                      conv_body(wo, g_Wof, n4);
}

// ---------------------------------------------------------------------------
// HMMA GEMM body, plain fp16 (1 MMA per product): C = Af @ Wf^T + bias.
// Block tile 128x128, BK=64; 8 warps = 2(M) x 4(N), each 64x32 (acc 64 regs).
// 2-stage cp.async pipeline; 2 CTAs/SM (smem 73728 B, regs <= 128).
// OMODE: 0 = fp32 out; 1 = fp16 single (x oscale).
// ---------------------------------------------------------------------------
#define SA2    72
#define ATILE2 (128 * SA2 * 2)             // 18432 B (A 128x64 tile)
#define BTILE2 (128 * SA2 * 2)             // 18432 B (W 128x64 tile)
#define STG3   (ATILE2 + BTILE2)           // 36864 B
#define GEMM_SMEM3 (2 * STG3)              // 73728 B
#define BKC2   64
#define NCH2   (DM / BKC2)                 // 16
#define OFF_AF 0
#define OFF_WF ATILE2

template <int OMODE>
__device__ __forceinline__ void gemm64_body(
    const __half* __restrict__ Af, const __half* __restrict__ Wf,
    const float* __restrict__ bias, float oscale, float* __restrict__ C,
    __half* __restrict__ Of)
{
    extern __shared__ char smem[];
    const uint32_t sb = smem_to_u32(smem);
    const int tid  = threadIdx.x;
    const int wid  = tid >> 5;
    const int lane = tid & 31;
    const int bm = blockIdx.y * 128;
    const int bn = blockIdx.x * 128;
    const int wm = (wid >> 2) * 64;       // 0 or 64
    const int wn = (wid & 3) * 32;        // 0,32,64,96

    // Loaders: thread t -> row t>>1 (128 rows), 64B half (4 x cp16)
    const int lrow  = tid >> 1;
    const int lhalf = (tid & 1) * 64;
    const char* gAf = (const char*)(Af + (size_t)(bm + lrow) * DM) + lhalf;
    const char* gWf = (const char*)(Wf + (size_t)(bn + lrow) * DM) + lhalf;
    const uint32_t so = (uint32_t)(lrow * SA2 * 2) + lhalf;

    auto load_chunk = [&](int c, int stg) {
        const uint32_t base = sb + stg * STG3;
        const int gb = c * (BKC2 * 2);
#pragma unroll
        for (int s = 0; s < 4; s++) {
            CP_ASYNC_16(base + OFF_AF + so + s * 16, gAf + gb + s * 16);
            CP_ASYNC_16(base + OFF_WF + so + s * 16, gWf + gb + s * 16);
        }
        CP_ASYNC_COMMIT();
    };

    const int grp = lane >> 3, rin = lane & 7;
    const int a_row = wm + (grp & 1) * 8 + rin;
    const int a_kof = (grp >> 1) * 8;
    const int b_row = wn + (grp >> 1) * 8 + rin;
    const int b_kof = (grp & 1) * 8;

    float acc[4][4][4];
#pragma unroll
    for (int i = 0; i < 4; i++)
#pragma unroll
        for (int j = 0; j < 4; j++)
#pragma unroll
            for (int r = 0; r < 4; r++) acc[i][j][r] = 0.0f;

    load_chunk(0, 0);

    for (int c = 0; c < NCH2; c++) {
        CP_ASYNC_WAIT0();
        __syncthreads();
        if (c + 1 < NCH2) load_chunk(c + 1, (c + 1) & 1);

        const uint32_t base = sb + (c & 1) * STG3;
#pragma unroll
        for (int k0 = 0; k0 < BKC2; k0 += 16) {
            uint32_t af[4][4];
#pragma unroll
            for (int i = 0; i < 4; i++) {
                uint32_t ad = base + OFF_AF +
                    (uint32_t)((a_row + i * 16) * SA2 + k0 + a_kof) * 2;
                ldsm_x4(af[i][0], af[i][1], af[i][2], af[i][3], ad);
            }
            uint32_t wf[4][2];
#pragma unroll
            for (int jp = 0; jp < 2; jp++) {
                uint32_t bd = base + OFF_WF +
                    (uint32_t)((b_row + jp * 16) * SA2 + k0 + b_kof) * 2;
                ldsm_x4(wf[jp * 2][0], wf[jp * 2][1],
                        wf[jp * 2 + 1][0], wf[jp * 2 + 1][1], bd);
            }
#pragma unroll
            for (int i = 0; i < 4; i++)
#pragma unroll
                for (int j = 0; j < 4; j++)
                    mma_f16(acc[i][j], af[i], wf[j][0], wf[j][1]);
        }
    }

    const int erow = bm + wm + (lane >> 2);
    const int ecol = bn + wn + (lane & 3) * 2;
#pragma unroll
    for (int i = 0; i < 4; i++) {
#pragma unroll
        for (int j = 0; j < 4; j++) {
            const int col = ecol + j * 8;
            const float b0 = bias[col], b1 = bias[col + 1];
            const size_t o0 = (size_t)(erow + i * 16) * DM + col;
            const size_t o1 = (size_t)(erow + i * 16 + 8) * DM + col;
            const float c0 = (acc[i][j][0] + b0) * oscale;
            const float c1 = (acc[i][j][1] + b1) * oscale;
            const float c2 = (acc[i][j][2] + b0) * oscale;
            const float c3 = (acc[i][j][3] + b1) * oscale;
            if (OMODE == 0) {
                *(float2*)(C + o0) = make_float2(c0, c1);
                *(float2*)(C + o1) = make_float2(c2, c3);
            } else {
                *(uint32_t*)(Of + o0) = packh(c0, c1);
                *(uint32_t*)(Of + o1) = packh(c2, c3);
            }
        }
    }
}

__global__ __launch_bounds__(256, 2) void qkv_gemm64(
    const float* __restrict__ bq, const float* __restrict__ bk,
    const float* __restrict__ bv)
{
    if (blockIdx.z == 0)
        gemm64_body<1>(g_Aqf, g_Wqf, bq, QSCALE, nullptr, g_Qf);
    else if (blockIdx.z == 1)
        gemm64_body<1>(g_Akf, g_Wkf, bk, 1.0f, nullptr, g_Kf);
    else
        gemm64_body<1>(g_Avf, g_Wvf, bv, 1.0f, nullptr, g_Vf);
}

__global__ __launch_bounds__(256, 2) void out_gemm64(
    const float* __restrict__ bo, float* __restrict__ out)
{
    gemm64_body<0>(g_Xf, g_Wof, bo, 1.0f, out, nullptr);
}

// ---------------------------------------------------------------------------
// HMMA flash attention, all-1-MMA fp16 (round 12 validated path, unchanged).
// Q single fp16 (pre-scaled, exp2 domain), K single fp16, V single fp16.
// ---------------------------------------------------------------------------
#define ASA 72
#define ATILE (128 * ASA * 2)
#define A_QF 0
#define A_ST0 ATILE
#define A_STAGE (2 * ATILE)                 // Kf, Vf
#define ATT_SMEM (ATILE + 2 * A_STAGE)      // 92160 B
#define NKT (SS / 128)

__global__ __launch_bounds__(256, 1) void attn_mma(
    const __half* __restrict__ Qf_, const __half* __restrict__ Kf_,
    const __half* __restrict__ Vf_, __half* __restrict__ Xf_)
{
    extern __shared__ char smem[];
    const uint32_t sb = smem_to_u32(smem);
    const int tid  = threadIdx.x;
    const int wid  = tid >> 5;
    const int lane = tid & 31;
    const int qm   = wid * 16;
    const int qb = blockIdx.x, h = blockIdx.y, b = blockIdx.z;
    const size_t qrow0 = (size_t)(b * SS + qb * 128);
    const size_t hoff  = (size_t)h * HD;

    // Q tile (single fp16) via cp.async (group 0)
#pragma unroll
    for (int i = 0; i < 4; i++) {
        int ci = tid + i * 256;
        int r = ci >> 3, cof = (ci & 7) * 16;
        uint32_t so = (uint32_t)(r * ASA * 2) + cof;
        CP_ASYNC_16(sb + A_QF + so,
                    (const char*)(Qf_ + (qrow0 + r) * DM + hoff) + cof);
    }
    CP_ASYNC_COMMIT();

    auto load_kv = [&](int kt, int stg) {
        const size_t k0 = (size_t)(b * SS + kt * 128);
        const uint32_t base = sb + A_ST0 + stg * A_STAGE;
#pragma unroll
        for (int i = 0; i < 4; i++) {
            int ci = tid + i * 256;
            int r = ci >> 3, cof = (ci & 7) * 16;
            uint32_t so = (uint32_t)(r * ASA * 2) + cof;
            const size_t g = (k0 + r) * DM + hoff;
            CP_ASYNC_16(base + 0 * ATILE + so, (const char*)(Kf_ + g) + cof);
            CP_ASYNC_16(base + 1 * ATILE + so, (const char*)(Vf_ + g) + cof);
        }
        CP_ASYNC_COMMIT();
    };

    load_kv(0, 0);    // group 1

    const int qrow_f = qm + (lane & 7) + ((lane >> 3) & 1) * 8;
    const int qkof_f = ((lane >> 4) & 1) * 8;
    const int krow_f = (lane & 7) + ((lane >> 4) & 1) * 8;
    const int kkof_f = ((lane >> 3) & 1) * 8;
    const int vrow_f = lane & 15;
    const int vcol_f = (lane >> 4) * 8;

    // Hoist Q fragments (Q group done after WAIT1)
    CP_ASYNC_WAIT1();
    __syncthreads();
    uint32_t qf[4][4];
#pragma unroll
    for (int ks = 0; ks < 4; ks++) {
        uint32_t qa = sb + A_QF + (uint32_t)(qrow_f * ASA + qkof_f + ks * 16) * 2;
        ldsm_x4(qf[ks][0], qf[ks][1], qf[ks][2], qf[ks][3], qa);
    }

    float O[8][4];
#pragma unroll
    for (int jo = 0; jo < 8; jo++)
#pragma unroll
        for (int r = 0; r < 4; r++) O[jo][r] = 0.0f;
    float M0 = -3.0e38f, M1 = -3.0e38f, L0 = 0.0f, L1 = 0.0f;

    for (int kt = 0; kt < NKT; kt++) {
        if (kt + 1 < NKT) {
            load_kv(kt + 1, (kt + 1) & 1);
            CP_ASYNC_WAIT1();
        } else {
            CP_ASYNC_WAIT0();
        }
        __syncthreads();
        const uint32_t stage = sb + A_ST0 + (kt & 1) * A_STAGE;

        // ---- S = Qf @ Kf^T  (1 MMA per n8-tile) ----
        float s[16][4];
#pragma unroll
        for (int j = 0; j < 16; j++)
#pragma unroll
            for (int r = 0; r < 4; r++) s[j][r] = 0.0f;

#pragma unroll
        for (int ks = 0; ks < 4; ks++) {
#pragma unroll
            for (int jp = 0; jp < 8; jp++) {
                uint32_t kf[4];
                uint32_t ka = stage + 0 * ATILE +
                    (uint32_t)((krow_f + jp * 16) * ASA + kkof_f + ks * 16) * 2;
                ldsm_x4(kf[0], kf[1], kf[2], kf[3], ka);
                mma_f16(s[jp * 2],     qf[ks], kf[0], kf[1]);
                mma_f16(s[jp * 2 + 1], qf[ks], kf[2], kf[3]);
            }
        }

        // ---- online softmax (exp2 domain) ----
        float mx0 = -3.0e38f, mx1 = -3.0e38f;
#pragma unroll
        for (int j = 0; j < 16; j++) {
            mx0 = fmaxf(mx0, fmaxf(s[j][0], s[j][1]));
            mx1 = fmaxf(mx1, fmaxf(s[j][2], s[j][3]));
        }
        mx0 = fmaxf(mx0, __shfl_xor_sync(0xffffffffu, mx0, 1));
        mx0 = fmaxf(mx0, __shfl_xor_sync(0xffffffffu, mx0, 2));
        mx1 = fmaxf(mx1, __shfl_xor_sync(0xffffffffu, mx1, 1));
        mx1 = fmaxf(mx1, __shfl_xor_sync(0xffffffffu, mx1, 2));

        const float Mn0 = fmaxf(M0, mx0), Mn1 = fmaxf(M1, mx1);
        const float f0 = ex2(M0 - Mn0), f1 = ex2(M1 - Mn1);
        M0 = Mn0; M1 = Mn1;

        float sum0 = 0.0f, sum1 = 0.0f;
#pragma unroll
        for (int j = 0; j < 16; j++) {
            s[j][0] = ex2(s[j][0] - M0);
            s[j][1] = ex2(s[j][1] - M0);
            s[j][2] = ex2(s[j][2] - M1);
            s[j][3] = ex2(s[j][3] - M1);
            sum0 += s[j][0] + s[j][1];
            sum1 += s[j][2] + s[j][3];
        }
        sum0 += __shfl_xor_sync(0xffffffffu, sum0, 1);
        sum0 += __shfl_xor_sync(0xffffffffu, sum0, 2);
        sum1 += __shfl_xor_sync(0xffffffffu, sum1, 1);
        sum1 += __shfl_xor_sync(0xffffffffu, sum1, 2);
        L0 = L0 * f0 + sum0;
        L1 = L1 * f1 + sum1;

#pragma unroll
        for (int jo = 0; jo < 8; jo++) {
            O[jo][0] *= f0; O[jo][1] *= f0;
            O[jo][2] *= f1; O[jo][3] *= f1;
        }

        // ---- O += Pf @ Vf  (1 MMA per n8-pair) ----
#pragma unroll
        for (int ks2 = 0; ks2 < 8; ks2++) {
            uint32_t ph[4];
            ph[0] = packh(s[2 * ks2][0],     s[2 * ks2][1]);
            ph[1] = packh(s[2 * ks2][2],     s[2 * ks2][3]);
            ph[2] = packh(s[2 * ks2 + 1][0], s[2 * ks2 + 1][1]);
            ph[3] = packh(s[2 * ks2 + 1][2], s[2 * ks2 + 1][3]);
#pragma unroll
            for (int nn = 0; nn < 4; nn++) {
                uint32_t vf[4];
                uint32_t va = stage + 1 * ATILE +
                    (uint32_t)((ks2 * 16 + vrow_f) * ASA + nn * 16 + vcol_f) * 2;
                ldsm_x4_t(vf[0], vf[1], vf[2], vf[3], va);
                mma_f16(O[nn * 2],     ph, vf[0], vf[1]);
                mma_f16(O[nn * 2 + 1], ph, vf[2], vf[3]);
            }
        }
        __syncthreads();
    }

    // ---- epilogue: normalize, single fp16 out ----
    const float il0 = 1.0f / L0, il1 = 1.0f / L1;
    const size_t r0 = qrow0 + qm + (lane >> 2);
    const size_t r1 = r0 + 8;
#pragma unroll
    for (int jo = 0; jo < 8; jo++) {
        const size_t col = hoff + jo * 8 + (lane & 3) * 2;
        *(uint32_t*)(Xf_ + r0 * DM + col) = packh(O[jo][0] * il0, O[jo][1] * il0);
        *(uint32_t*)(Xf_ + r1 * DM + col) = packh(O[jo][2] * il1, O[jo][3] * il1);
    }
}

// ---------------------------------------------------------------------------
extern "C" void kernel_launch(void* const* d_in, const int* in_sizes, int n_in,
                              void* d_out, int out_size)
{
    const float* query = (const float*)d_in[0];
    const float* key   = (const float*)d_in[1];
    const float* value = (const float*)d_in[2];
    const float* Wq    = (const float*)d_in[3];
    const float* bq    = (const float*)d_in[4];
    const float* Wk    = (const float*)d_in[5];
    const float* bk    = (const float*)d_in[6];
    const float* Wv    = (const float*)d_in[7];
    const float* bv    = (const float*)d_in[8];
    const float* Wo    = (const float*)d_in[9];
    const float* bo    = (const float*)d_in[10];
    float* out = (float*)d_out;

    __half *qf, *kf, *vf, *xf;
    cudaGetSymbolAddress((void**)&qf, g_Qf);
    cudaGetSymbolAddress((void**)&kf, g_Kf);
    cudaGetSymbolAddress((void**)&vf, g_Vf);
    cudaGetSymbolAddress((void**)&xf, g_Xf);

    cudaFuncSetAttribute(qkv_gemm64,
                         cudaFuncAttributeMaxDynamicSharedMemorySize, GEMM_SMEM3);
    cudaFuncSetAttribute(out_gemm64,
                         cudaFuncAttributeMaxDynamicSharedMemorySize, GEMM_SMEM3);
    cudaFuncSetAttribute(attn_mma,
                         cudaFuncAttributeMaxDynamicSharedMemorySize, ATT_SMEM);

    conv_inputs_kernel<<<dim3(2048, 1, 3), 256>>>(query, key, value);
    conv_weights_kernel<<<dim3(512, 1, 4), 256>>>(Wq, Wk, Wv, Wo);

    qkv_gemm64<<<dim3(DM / 128, MROWS / 128, 3), 256, GEMM_SMEM3>>>(bq, bk, bv);

    attn_mma<<<dim3(SS / 128, HH, BB), 256, ATT_SMEM>>>(qf, kf, vf, xf);

    out_gemm64<<<dim3(DM / 128, MROWS / 128), 256, GEMM_SMEM3>>>(bo, out);
}